// round 1
// baseline (speedup 1.0000x reference)
#include <cuda_runtime.h>
#include <math.h>

// Shapes
#define Bb 32
#define Tt 8
#define Nn 512
#define Ff 4
#define Hh 64
#define CO 12
#define NODES (Bb*Tt*Nn)          // 131072
#define SEQS  (Bb*Nn)             // 16384

// Scratch (device globals: allocation-free per harness rules)
__device__ float  g_Wx[(size_t)NODES*Hh];      // 33.5 MB : Wx [B,T,N,H]
__device__ float4 g_Esc[NODES];                // {E1s,E2s,E1d,E2d} per node
__device__ float  g_gat[(size_t)NODES*Hh];     // 33.5 MB : gat_out [B,T,N,H]
__device__ float  g_gatesx[(size_t)NODES*12];  // gates_x  [(s*8+t), 12]
__device__ float  g_gru[(size_t)SEQS*Tt*Ff];   // gru_out [B*N, T, 4]

// ---------------------------------------------------------------------------
// Kernel A: Wx = x @ gat_W ; a_src/a_dst dots ; exp factors
// blockDim (64,4): x = h index, y = node-in-block
// ---------------------------------------------------------------------------
__global__ void gat_proj_kernel(const float* __restrict__ x,
                                const float* __restrict__ W,
                                const float* __restrict__ attS,
                                const float* __restrict__ attD) {
    __shared__ float Ws[Ff*Hh];
    __shared__ float aS[Hh], aD[Hh];
    __shared__ float red[4][2][2];
    int hx = threadIdx.x;           // 0..63
    int ny = threadIdx.y;           // 0..3
    int tid = ny*64 + hx;
    if (tid < 256) Ws[tid] = W[tid];
    if (tid < 64)  aS[tid] = attS[tid];
    else if (tid < 128) aD[tid-64] = attD[tid-64];
    __syncthreads();

    int node = blockIdx.x*4 + ny;
    float4 xv = *(const float4*)(x + (size_t)node*4);
    float wx = xv.x*Ws[hx] + xv.y*Ws[64+hx] + xv.z*Ws[128+hx] + xv.w*Ws[192+hx];
    g_Wx[(size_t)node*Hh + hx] = wx;

    float vs = wx * aS[hx];
    float vd = wx * aD[hx];
    #pragma unroll
    for (int o = 16; o > 0; o >>= 1) {
        vs += __shfl_down_sync(0xffffffffu, vs, o);
        vd += __shfl_down_sync(0xffffffffu, vd, o);
    }
    if ((hx & 31) == 0) { red[ny][hx>>5][0] = vs; red[ny][hx>>5][1] = vd; }
    __syncthreads();
    if (hx == 0) {
        float as = red[ny][0][0] + red[ny][1][0];
        float ad = red[ny][0][1] + red[ny][1][1];
        g_Esc[node] = make_float4(expf(as), expf(0.2f*as), expf(ad), expf(0.2f*ad));
    }
}

// ---------------------------------------------------------------------------
// Kernel B: masked softmax attention + aggregate (the dominant kernel)
// grid (16, B*T); block 256 = 32 i x 8 h-groups; j chunked by 64 via smem.
// w_ij = mask ? ((d+s>0) ? exp(d)exp(s) : exp(.2d)exp(.2s)) : 0
// ---------------------------------------------------------------------------
__global__ __launch_bounds__(256) void gat_attn_kernel(const float* __restrict__ adj,
                                                       const float* __restrict__ bias) {
    __shared__ float WxS[64*Hh];      // 16 KB
    __shared__ float adjS[64*32];     // 8 KB  (transposed tile: [j][i])
    __shared__ float E1sS[64], E2sS[64];

    int bt  = blockIdx.y;             // 0..255
    int i0  = blockIdx.x * 32;
    int tid = threadIdx.x;
    int il  = tid & 31;               // i within tile (lane)
    int hg  = tid >> 5;               // h-group (warp id)
    int i   = i0 + il;
    int nodeI = bt*Nn + i;

    float4 ei = g_Esc[nodeI];
    float e1d = ei.z, e2d = ei.w;

    float acc[8];
    #pragma unroll
    for (int k = 0; k < 8; k++) acc[k] = 0.0f;
    float den = 0.0f;

    const float* adjbt = adj + (size_t)bt*Nn*Nn;

    for (int j0 = 0; j0 < Nn; j0 += 64) {
        // Wx tile: 64 rows x 64 h = 1024 float4
        {
            const float4* src = (const float4*)(g_Wx + (size_t)(bt*Nn + j0)*Hh);
            float4* dst = (float4*)WxS;
            #pragma unroll
            for (int k = 0; k < 4; k++) dst[tid + k*256] = src[tid + k*256];
        }
        // adj tile (transposed access): adjS[jj][ii] = adj[bt, j0+jj, i0+ii]
        #pragma unroll
        for (int k = 0; k < 2; k++) {
            int idx = tid + k*256;       // 0..511 float4s
            int jj = idx >> 3, q = idx & 7;
            ((float4*)adjS)[idx] = *(const float4*)(adjbt + (size_t)(j0+jj)*Nn + i0 + q*4);
        }
        if (tid < 64) {
            float4 e = g_Esc[bt*Nn + j0 + tid];
            E1sS[tid] = e.x; E2sS[tid] = e.y;
        }
        __syncthreads();

        #pragma unroll 4
        for (int jj = 0; jj < 64; jj++) {
            float a  = adjS[jj*32 + il];
            float s1 = E1sS[jj];
            float s2 = E2sS[jj];
            float p1 = e1d * s1;                 // exp(d+s)
            float w  = (p1 > 1.0f) ? p1 : e2d * s2;  // sign(d+s) via p1>1
            bool  m  = (a != 0.0f) || (j0 + jj == i);
            w = m ? w : 0.0f;
            den += w;
            const float4* wr = (const float4*)(WxS + jj*Hh + hg*8);
            float4 w0 = wr[0], w1 = wr[1];
            acc[0] = fmaf(w, w0.x, acc[0]);
            acc[1] = fmaf(w, w0.y, acc[1]);
            acc[2] = fmaf(w, w0.z, acc[2]);
            acc[3] = fmaf(w, w0.w, acc[3]);
            acc[4] = fmaf(w, w1.x, acc[4]);
            acc[5] = fmaf(w, w1.y, acc[5]);
            acc[6] = fmaf(w, w1.z, acc[6]);
            acc[7] = fmaf(w, w1.w, acc[7]);
        }
        __syncthreads();
    }

    float inv = 1.0f / den;
    float* out = g_gat + (size_t)nodeI*Hh + hg*8;
    #pragma unroll
    for (int k = 0; k < 8; k++) out[k] = acc[k]*inv + bias[hg*8 + k];
}

// ---------------------------------------------------------------------------
// Kernel C1: gates_x[row,12] = b_ih + seq[row,:] @ W_ih^T, row = s*8+t
// (seq is the RAW reshape of gat_out: seq[row*64 + h])
// blockDim 192 = 16 rows x 12 gates
// ---------------------------------------------------------------------------
__global__ void gru_gates_kernel(const float* __restrict__ Wih,
                                 const float* __restrict__ bih) {
    __shared__ float rowS[16*64];
    __shared__ float WS[12*64];
    __shared__ float bS[12];
    int tid = threadIdx.x;
    int row0 = blockIdx.x * 16;
    for (int k = tid; k < 768; k += 192) WS[k] = Wih[k];
    if (tid < 12) bS[tid] = bih[tid];
    for (int k = tid; k < 1024; k += 192) rowS[k] = g_gat[(size_t)row0*64 + k];
    __syncthreads();

    int r = tid / 12, g = tid % 12;
    float accv = bS[g];
    const float* xr = rowS + r*64;
    const float* wr = WS + g*64;
    #pragma unroll 16
    for (int h = 0; h < 64; h++) accv = fmaf(xr[h], wr[h], accv);
    g_gatesx[(size_t)(row0 + r)*12 + g] = accv;
}

// ---------------------------------------------------------------------------
// Kernel C2: GRU recurrence, hidden=4, T=8. One thread per sequence.
// ---------------------------------------------------------------------------
__global__ void gru_scan_kernel(const float* __restrict__ Whh,
                                const float* __restrict__ bhh) {
    __shared__ float WS[48], bS[12];
    int tid = threadIdx.x;
    if (tid < 48) WS[tid] = Whh[tid];
    if (tid < 12) bS[tid] = bhh[tid];
    __syncthreads();

    int s = blockIdx.x*blockDim.x + tid;   // 0..16383
    float h[4] = {0.f, 0.f, 0.f, 0.f};
    for (int t = 0; t < Tt; t++) {
        const float* gx = g_gatesx + (size_t)(s*Tt + t)*12;
        float4 g0 = *(const float4*)(gx);
        float4 g1 = *(const float4*)(gx + 4);
        float4 g2 = *(const float4*)(gx + 8);
        float gxa[12] = {g0.x,g0.y,g0.z,g0.w, g1.x,g1.y,g1.z,g1.w, g2.x,g2.y,g2.z,g2.w};
        float hh[12];
        #pragma unroll
        for (int g = 0; g < 12; g++)
            hh[g] = bS[g] + WS[g*4]*h[0] + WS[g*4+1]*h[1] + WS[g*4+2]*h[2] + WS[g*4+3]*h[3];
        #pragma unroll
        for (int f = 0; f < 4; f++) {
            float r = 1.0f/(1.0f + expf(-(gxa[f]   + hh[f])));
            float z = 1.0f/(1.0f + expf(-(gxa[4+f] + hh[4+f])));
            float nc = tanhf(gxa[8+f] + r*hh[8+f]);
            h[f] = (1.0f - z)*nc + z*h[f];
        }
        *(float4*)(g_gru + (size_t)(s*Tt + t)*4) = make_float4(h[0],h[1],h[2],h[3]);
    }
}

// ---------------------------------------------------------------------------
// Kernel D: Conv2d(T=8 -> 12, 3x3, pad 1) over (H=N, W=4) fused with
// Linear(4 -> 2). One thread per (b, co, n).
// g[b,ci,n,f] = g_gru[((b*512+n)*8 + ci)*4 + f]
// ---------------------------------------------------------------------------
__global__ void conv_out_kernel(const float* __restrict__ convW,
                                const float* __restrict__ convb,
                                const float* __restrict__ outW,
                                const float* __restrict__ outb,
                                float* __restrict__ out) {
    __shared__ float cw[CO*Tt*9];   // 864
    __shared__ float cb[CO], ow[8], ob[2];
    int tid = threadIdx.x;
    for (int k = tid; k < CO*Tt*9; k += 256) cw[k] = convW[k];
    if (tid < CO) cb[tid] = convb[tid];
    if (tid < 8)  ow[tid] = outW[tid];
    if (tid < 2)  ob[tid] = outb[tid];
    __syncthreads();

    int idx = blockIdx.x*256 + tid;        // < 32*12*512 = 196608
    int n  = idx & 511;
    int co = (idx >> 9) % CO;
    int b  = idx / (512*CO);

    float y0 = cb[co], y1 = y0, y2 = y0, y3 = y0;
    #pragma unroll
    for (int kh = 0; kh < 3; kh++) {
        int nn = n + kh - 1;
        if (nn < 0 || nn >= Nn) continue;
        const float* gbase = g_gru + (size_t)(b*Nn + nn)*(Tt*Ff);
        #pragma unroll
        for (int ci = 0; ci < Tt; ci++) {
            float4 gv = *(const float4*)(gbase + ci*4);
            const float* wk = cw + ((co*Tt + ci)*3 + kh)*3;
            float w0 = wk[0], w1 = wk[1], w2 = wk[2];
            // kw=0 -> uses g[f-1]
            y1 = fmaf(w0, gv.x, y1); y2 = fmaf(w0, gv.y, y2); y3 = fmaf(w0, gv.z, y3);
            // kw=1 -> g[f]
            y0 = fmaf(w1, gv.x, y0); y1 = fmaf(w1, gv.y, y1);
            y2 = fmaf(w1, gv.z, y2); y3 = fmaf(w1, gv.w, y3);
            // kw=2 -> g[f+1]
            y0 = fmaf(w2, gv.y, y0); y1 = fmaf(w2, gv.z, y1); y2 = fmaf(w2, gv.w, y2);
        }
    }
    float o0 = ob[0] + y0*ow[0] + y1*ow[1] + y2*ow[2] + y3*ow[3];
    float o1 = ob[1] + y0*ow[4] + y1*ow[5] + y2*ow[6] + y3*ow[7];
    ((float2*)out)[idx] = make_float2(o0, o1);
}

// ---------------------------------------------------------------------------
extern "C" void kernel_launch(void* const* d_in, const int* in_sizes, int n_in,
                              void* d_out, int out_size) {
    const float* x        = (const float*)d_in[0];
    const float* adj      = (const float*)d_in[1];
    const float* gat_W    = (const float*)d_in[2];
    const float* att_src  = (const float*)d_in[3];
    const float* att_dst  = (const float*)d_in[4];
    const float* gat_bias = (const float*)d_in[5];
    const float* gru_Wih  = (const float*)d_in[6];
    const float* gru_Whh  = (const float*)d_in[7];
    const float* gru_bih  = (const float*)d_in[8];
    const float* gru_bhh  = (const float*)d_in[9];
    const float* conv_W   = (const float*)d_in[10];
    const float* conv_b   = (const float*)d_in[11];
    const float* out_W    = (const float*)d_in[12];
    const float* out_b    = (const float*)d_in[13];
    float* out = (float*)d_out;

    // A: projection + exp factors
    gat_proj_kernel<<<NODES/4, dim3(64,4)>>>(x, gat_W, att_src, att_dst);
    // B: attention aggregate
    gat_attn_kernel<<<dim3(16, Bb*Tt), 256>>>(adj, gat_bias);
    // C1: GRU input gates
    gru_gates_kernel<<<NODES/16, 192>>>(gru_Wih, gru_bih);
    // C2: GRU recurrence
    gru_scan_kernel<<<SEQS/256, 256>>>(gru_Whh, gru_bhh);
    // D: conv + linear
    conv_out_kernel<<<(Bb*CO*Nn)/256, 256>>>(conv_W, conv_b, out_W, out_b, out);
}

// round 3
// speedup vs baseline: 2.1036x; 2.1036x over previous
#include <cuda_runtime.h>
#include <math.h>
#include <cstdint>

// Shapes
#define Bb 32
#define Tt 8
#define Nn 512
#define Ff 4
#define Hh 64
#define CO 12
#define NA 72                       // 64 h + 1 ones col (denominator) + 7 zero pad
#define NODES (Bb*Tt*Nn)            // 131072
#define SEQS  (Bb*Nn)               // 16384

// Scratch (device globals)
__device__ float  g_WxT[(size_t)Bb*Tt*NA*Nn];   // [bt][72][512], tf32-rounded
__device__ float4 g_Esc[NODES];                 // {e^s, e^.2s, e^d, e^.2d}
__device__ float  g_gat[(size_t)NODES*Hh];      // gat_out [B,T,N,H]
__device__ float  g_gatesx[(size_t)NODES*12];
__device__ float  g_gru[(size_t)SEQS*Tt*Ff];

// ---------------- helpers ----------------
__device__ __forceinline__ uint32_t cvt_tf32(float x) {
    uint32_t r;
    asm("cvt.rna.tf32.f32 %0, %1;" : "=r"(r) : "f"(x));
    return r;
}
__device__ __forceinline__ void mma_tf32(float c[4], const uint32_t a[4],
                                         uint32_t b0, uint32_t b1) {
    asm volatile(
        "mma.sync.aligned.m16n8k8.row.col.f32.tf32.tf32.f32 "
        "{%0,%1,%2,%3}, {%4,%5,%6,%7}, {%8,%9}, {%0,%1,%2,%3};"
        : "+f"(c[0]), "+f"(c[1]), "+f"(c[2]), "+f"(c[3])
        : "r"(a[0]), "r"(a[1]), "r"(a[2]), "r"(a[3]), "r"(b0), "r"(b1));
}

// ---------------------------------------------------------------------------
// Kernel A: Wx = x @ gat_W, stored transposed per bt as [72][512] (tf32-rounded;
// row 64 = ones for the softmax denominator, rows 65..71 zero), plus per-node
// exp factors. grid 2048 = bt(256) x jchunk(8); block 256.
// ---------------------------------------------------------------------------
__global__ __launch_bounds__(256) void gat_proj_kernel(const float* __restrict__ x,
                                const float* __restrict__ W,
                                const float* __restrict__ attS,
                                const float* __restrict__ attD) {
    __shared__ float Ws[Ff*Hh];
    __shared__ float aS[Hh], aD[Hh];
    __shared__ float WxS[64][68];
    int tid = threadIdx.x;
    int bt = blockIdx.x >> 3;
    int j0 = (blockIdx.x & 7) * 64;
    if (tid < 256) Ws[tid] = W[tid];
    if (tid < 64)  aS[tid] = attS[tid];
    else if (tid < 128) aD[tid-64] = attD[tid-64];
    __syncthreads();

    int jj = tid >> 2, part = tid & 3;
    int node = bt*Nn + j0 + jj;
    float4 xv = *(const float4*)(x + (size_t)node*4);
    float vs = 0.f, vd = 0.f;
    #pragma unroll
    for (int k = 0; k < 16; k++) {
        int h = part*16 + k;
        float wx = xv.x*Ws[h] + xv.y*Ws[64+h] + xv.z*Ws[128+h] + xv.w*Ws[192+h];
        WxS[jj][h] = wx;
        vs = fmaf(wx, aS[h], vs);
        vd = fmaf(wx, aD[h], vd);
    }
    vs += __shfl_down_sync(0xffffffffu, vs, 2);
    vs += __shfl_down_sync(0xffffffffu, vs, 1);
    vd += __shfl_down_sync(0xffffffffu, vd, 2);
    vd += __shfl_down_sync(0xffffffffu, vd, 1);
    if (part == 0)
        g_Esc[node] = make_float4(expf(vs), expf(0.2f*vs), expf(vd), expf(0.2f*vd));
    __syncthreads();

    // transposed, tf32-rounded write
    int h = tid >> 2, q = tid & 3;
    float* dst = g_WxT + ((size_t)bt*NA + h)*Nn + j0 + q*16;
    #pragma unroll
    for (int v = 0; v < 4; v++) {
        uint4 f;
        f.x = cvt_tf32(WxS[q*16+v*4+0][h]);
        f.y = cvt_tf32(WxS[q*16+v*4+1][h]);
        f.z = cvt_tf32(WxS[q*16+v*4+2][h]);
        f.w = cvt_tf32(WxS[q*16+v*4+3][h]);
        *(uint4*)(dst + v*4) = f;
    }
    // augmentation rows 64..71
    if (tid < 128) {
        int r = tid >> 4, jq = tid & 15;
        float val = (r == 0) ? 1.0f : 0.0f;
        *(float4*)(g_WxT + ((size_t)bt*NA + 64 + r)*Nn + j0 + jq*4) =
            make_float4(val, val, val, val);
    }
}

// ---------------------------------------------------------------------------
// Kernel B: attention aggregate via mma.sync tf32 (m16n8k8).
// grid (4 i-tiles, 256 bt); 128 threads = 4 warps x 32 i-rows.
// A operand (weights w) generated directly in fragment registers from gmem adj.
// B operand = WxT chunk [72 h][32 j] staged in smem (conflict-free frag reads).
// ---------------------------------------------------------------------------
__global__ __launch_bounds__(128, 3)
void gat_attn_mma(const float* __restrict__ adj, const float* __restrict__ bias) {
    __shared__ float smB[NA*36];        // [h][36] : 10.4 KB
    __shared__ float E1sS[32], E2sS[32];
    __shared__ float biasS[64];

    int bt = blockIdx.y;
    int i0 = blockIdx.x * 128;
    int tid = threadIdx.x, wid = tid >> 5, lane = tid & 31;
    int lr = lane >> 2, lc = lane & 3;
    int ibase = i0 + wid*32;            // this warp's first i row (within bt)

    if (tid < 64) biasS[tid] = bias[tid];

    // e^d factors for this thread's 4 rows (lr + 8m)
    float e1d[4], e2d[4];
    #pragma unroll
    for (int m = 0; m < 4; m++) {
        float4 e = g_Esc[bt*Nn + ibase + lr + 8*m];
        e1d[m] = e.z; e2d[m] = e.w;
    }

    float acc[2][9][4];
    #pragma unroll
    for (int f = 0; f < 2; f++)
        #pragma unroll
        for (int nf = 0; nf < 9; nf++)
            #pragma unroll
            for (int r = 0; r < 4; r++) acc[f][nf][r] = 0.0f;

    const float* adjbt = adj + (size_t)bt*Nn*Nn;
    const float* WxTbt = g_WxT + (size_t)bt*NA*Nn;

    for (int c = 0; c < 16; c++) {
        int j0 = c * 32;
        // 1) adj gmem loads (independent of smem) — full-sector access pattern
        float av[4][8];
        #pragma unroll
        for (int ks = 0; ks < 4; ks++) {
            const float* r1 = adjbt + (size_t)(j0 + 8*ks + lc)*Nn + ibase + lr;
            const float* r2 = r1 + 4*Nn;
            #pragma unroll
            for (int f = 0; f < 2; f++) {
                av[ks][f*4+0] = r1[16*f];
                av[ks][f*4+1] = r1[16*f + 8];
                av[ks][f*4+2] = r2[16*f];
                av[ks][f*4+3] = r2[16*f + 8];
            }
        }
        // 2) protect smem restage
        __syncthreads();
        // 3) stage B tile [72 h][32 j] (stride 36) + exp factors
        #pragma unroll
        for (int t = 0; t < 5; t++) {
            int idx = tid + t*128;
            if (idx < 576) {
                int h = idx >> 3, q = idx & 7;
                float4 v = *(const float4*)(WxTbt + (size_t)h*Nn + j0 + q*4);
                *(float4*)(smB + h*36 + q*4) = v;
            }
        }
        if (tid < 32) {
            float4 e = g_Esc[bt*Nn + j0 + tid];
            E1sS[tid] = e.x; E2sS[tid] = e.y;
        }
        __syncthreads();

        // 4) per K=8 step: build A fragments in regs, LDS B frags, MMA
        #pragma unroll
        for (int ks = 0; ks < 4; ks++) {
            int jl = 8*ks + lc;
            float E1a = E1sS[jl],   E2a = E2sS[jl];
            float E1b = E1sS[jl+4], E2b = E2sS[jl+4];
            uint32_t A[2][4];
            #pragma unroll
            for (int f = 0; f < 2; f++) {
                #pragma unroll
                for (int t = 0; t < 4; t++) {
                    int m = 2*f + (t & 1);
                    float E1 = (t < 2) ? E1a : E1b;
                    float E2 = (t < 2) ? E2a : E2b;
                    float a  = av[ks][f*4+t];
                    float p1 = e1d[m] * E1;
                    float w  = (p1 > 1.0f) ? p1 : e2d[m] * E2;
                    int ig = ibase + lr + 16*f + 8*(t & 1);
                    int jg = j0 + jl + ((t < 2) ? 0 : 4);
                    w = ((a != 0.0f) || (ig == jg)) ? w : 0.0f;
                    A[f][t] = cvt_tf32(w);
                }
            }
            #pragma unroll
            for (int nf = 0; nf < 9; nf++) {
                uint32_t b0 = __float_as_uint(smB[(lr + 8*nf)*36 + jl]);
                uint32_t b1 = __float_as_uint(smB[(lr + 8*nf)*36 + jl + 4]);
                mma_tf32(acc[0][nf], A[0], b0, b1);
                mma_tf32(acc[1][nf], A[1], b0, b1);
            }
        }
    }

    // epilogue: denominators live in nf=8, col 64 (lanes with lc==0)
    const unsigned FULL = 0xffffffffu;
    float inv[4];
    {
        int src = lane & 28;
        float d0 = __shfl_sync(FULL, acc[0][8][0], src);
        float d1 = __shfl_sync(FULL, acc[0][8][2], src);
        float d2 = __shfl_sync(FULL, acc[1][8][0], src);
        float d3 = __shfl_sync(FULL, acc[1][8][2], src);
        inv[0] = 1.0f/d0; inv[1] = 1.0f/d1; inv[2] = 1.0f/d2; inv[3] = 1.0f/d3;
    }
    #pragma unroll
    for (int f = 0; f < 2; f++) {
        #pragma unroll
        for (int nf = 0; nf < 8; nf++) {
            int col = 8*nf + 2*lc;
            float b0 = biasS[col], b1 = biasS[col+1];
            int rowA = ibase + lr + 16*f;
            float2 v0 = make_float2(acc[f][nf][0]*inv[2*f]   + b0,
                                    acc[f][nf][1]*inv[2*f]   + b1);
            float2 v1 = make_float2(acc[f][nf][2]*inv[2*f+1] + b0,
                                    acc[f][nf][3]*inv[2*f+1] + b1);
            *(float2*)(g_gat + (size_t)(bt*Nn + rowA)*64 + col)     = v0;
            *(float2*)(g_gat + (size_t)(bt*Nn + rowA + 8)*64 + col) = v1;
        }
    }
}

// ---------------------------------------------------------------------------
// Kernel C1: gates_x = seq @ W_ih^T + b_ih  (seq = raw view of gat_out)
// ---------------------------------------------------------------------------
__global__ void gru_gates_kernel(const float* __restrict__ Wih,
                                 const float* __restrict__ bih) {
    __shared__ float rowS[16*64];
    __shared__ float WS[12*64];
    __shared__ float bS[12];
    int tid = threadIdx.x;
    int row0 = blockIdx.x * 16;
    for (int k = tid; k < 768; k += 192) WS[k] = Wih[k];
    if (tid < 12) bS[tid] = bih[tid];
    for (int k = tid; k < 1024; k += 192) rowS[k] = g_gat[(size_t)row0*64 + k];
    __syncthreads();

    int r = tid / 12, g = tid % 12;
    float accv = bS[g];
    const float* xr = rowS + r*64;
    const float* wr = WS + g*64;
    #pragma unroll 16
    for (int h = 0; h < 64; h++) accv = fmaf(xr[h], wr[h], accv);
    g_gatesx[(size_t)(row0 + r)*12 + g] = accv;
}

// ---------------------------------------------------------------------------
// Kernel C2: GRU recurrence, hidden=4, T=8. One thread per sequence.
// ---------------------------------------------------------------------------
__global__ void gru_scan_kernel(const float* __restrict__ Whh,
                                const float* __restrict__ bhh) {
    __shared__ float WS[48], bS[12];
    int tid = threadIdx.x;
    if (tid < 48) WS[tid] = Whh[tid];
    if (tid < 12) bS[tid] = bhh[tid];
    __syncthreads();

    int s = blockIdx.x*blockDim.x + tid;   // 0..16383
    float h[4] = {0.f, 0.f, 0.f, 0.f};
    for (int t = 0; t < Tt; t++) {
        const float* gx = g_gatesx + (size_t)(s*Tt + t)*12;
        float4 g0 = *(const float4*)(gx);
        float4 g1 = *(const float4*)(gx + 4);
        float4 g2 = *(const float4*)(gx + 8);
        float gxa[12] = {g0.x,g0.y,g0.z,g0.w, g1.x,g1.y,g1.z,g1.w, g2.x,g2.y,g2.z,g2.w};
        float hh[12];
        #pragma unroll
        for (int g = 0; g < 12; g++)
            hh[g] = bS[g] + WS[g*4]*h[0] + WS[g*4+1]*h[1] + WS[g*4+2]*h[2] + WS[g*4+3]*h[3];
        #pragma unroll
        for (int f = 0; f < 4; f++) {
            float r = 1.0f/(1.0f + expf(-(gxa[f]   + hh[f])));
            float z = 1.0f/(1.0f + expf(-(gxa[4+f] + hh[4+f])));
            float nc = tanhf(gxa[8+f] + r*hh[8+f]);
            h[f] = (1.0f - z)*nc + z*h[f];
        }
        *(float4*)(g_gru + (size_t)(s*Tt + t)*4) = make_float4(h[0],h[1],h[2],h[3]);
    }
}

// ---------------------------------------------------------------------------
// Kernel D: Conv2d(8 -> 12, 3x3, pad 1) over (N, 4) fused with Linear(4 -> 2)
// ---------------------------------------------------------------------------
__global__ void conv_out_kernel(const float* __restrict__ convW,
                                const float* __restrict__ convb,
                                const float* __restrict__ outW,
                                const float* __restrict__ outb,
                                float* __restrict__ out) {
    __shared__ float cw[CO*Tt*9];
    __shared__ float cb[CO], ow[8], ob[2];
    int tid = threadIdx.x;
    for (int k = tid; k < CO*Tt*9; k += 256) cw[k] = convW[k];
    if (tid < CO) cb[tid] = convb[tid];
    if (tid < 8)  ow[tid] = outW[tid];
    if (tid < 2)  ob[tid] = outb[tid];
    __syncthreads();

    int idx = blockIdx.x*256 + tid;
    int n  = idx & 511;
    int co = (idx >> 9) % CO;
    int b  = idx / (512*CO);

    float y0 = cb[co], y1 = y0, y2 = y0, y3 = y0;
    #pragma unroll
    for (int kh = 0; kh < 3; kh++) {
        int nn = n + kh - 1;
        if (nn < 0 || nn >= Nn) continue;
        const float* gbase = g_gru + (size_t)(b*Nn + nn)*(Tt*Ff);
        #pragma unroll
        for (int ci = 0; ci < Tt; ci++) {
            float4 gv = *(const float4*)(gbase + ci*4);
            const float* wk = cw + ((co*Tt + ci)*3 + kh)*3;
            float w0 = wk[0], w1 = wk[1], w2 = wk[2];
            y1 = fmaf(w0, gv.x, y1); y2 = fmaf(w0, gv.y, y2); y3 = fmaf(w0, gv.z, y3);
            y0 = fmaf(w1, gv.x, y0); y1 = fmaf(w1, gv.y, y1);
            y2 = fmaf(w1, gv.z, y2); y3 = fmaf(w1, gv.w, y3);
            y0 = fmaf(w2, gv.y, y0); y1 = fmaf(w2, gv.z, y1); y2 = fmaf(w2, gv.w, y2);
        }
    }
    float o0 = ob[0] + y0*ow[0] + y1*ow[1] + y2*ow[2] + y3*ow[3];
    float o1 = ob[1] + y0*ow[4] + y1*ow[5] + y2*ow[6] + y3*ow[7];
    ((float2*)out)[idx] = make_float2(o0, o1);
}

// ---------------------------------------------------------------------------
extern "C" void kernel_launch(void* const* d_in, const int* in_sizes, int n_in,
                              void* d_out, int out_size) {
    const float* x        = (const float*)d_in[0];
    const float* adj      = (const float*)d_in[1];
    const float* gat_W    = (const float*)d_in[2];
    const float* att_src  = (const float*)d_in[3];
    const float* att_dst  = (const float*)d_in[4];
    const float* gat_bias = (const float*)d_in[5];
    const float* gru_Wih  = (const float*)d_in[6];
    const float* gru_Whh  = (const float*)d_in[7];
    const float* gru_bih  = (const float*)d_in[8];
    const float* gru_bhh  = (const float*)d_in[9];
    const float* conv_W   = (const float*)d_in[10];
    const float* conv_b   = (const float*)d_in[11];
    const float* out_W    = (const float*)d_in[12];
    const float* out_b    = (const float*)d_in[13];
    float* out = (float*)d_out;

    gat_proj_kernel<<<2048, 256>>>(x, gat_W, att_src, att_dst);
    gat_attn_mma<<<dim3(4, Bb*Tt), 128>>>(adj, gat_bias);
    gru_gates_kernel<<<NODES/16, 192>>>(gru_Wih, gru_bih);
    gru_scan_kernel<<<128, 128>>>(gru_Whh, gru_bhh);
    conv_out_kernel<<<(Bb*CO*Nn)/256, 256>>>(conv_W, conv_b, out_W, out_b, out);
}

// round 4
// speedup vs baseline: 3.0309x; 1.4408x over previous
#include <cuda_runtime.h>
#include <math.h>
#include <cstdint>

// Shapes
#define Bb 32
#define Tt 8
#define Nn 512
#define Ff 4
#define Hh 64
#define CO 12
#define NA 72                       // 64 h + 1 ones col (denominator) + 7 zero pad
#define NODES (Bb*Tt*Nn)            // 131072
#define SEQS  (Bb*Nn)               // 16384

// Scratch (device globals)
__device__ float  g_WxT[(size_t)Bb*Tt*NA*Nn];   // [bt][72][512], tf32-rounded
__device__ float4 g_Esc[NODES];                 // {e^s, e^.2s, e^d, e^.2d}
__device__ float  g_gat[(size_t)NODES*Hh];      // gat_out [B,T,N,H]
__device__ float  g_gatesx[(size_t)NODES*12];
__device__ float  g_gru[(size_t)SEQS*Tt*Ff];

// ---------------- helpers ----------------
__device__ __forceinline__ uint32_t cvt_tf32(float x) {
    uint32_t r;
    asm("cvt.rna.tf32.f32 %0, %1;" : "=r"(r) : "f"(x));
    return r;
}
__device__ __forceinline__ void mma_tf32(float c[4], const uint32_t a[4],
                                         uint32_t b0, uint32_t b1) {
    asm volatile(
        "mma.sync.aligned.m16n8k8.row.col.f32.tf32.tf32.f32 "
        "{%0,%1,%2,%3}, {%4,%5,%6,%7}, {%8,%9}, {%0,%1,%2,%3};"
        : "+f"(c[0]), "+f"(c[1]), "+f"(c[2]), "+f"(c[3])
        : "r"(a[0]), "r"(a[1]), "r"(a[2]), "r"(a[3]), "r"(b0), "r"(b1));
}
__device__ __forceinline__ float fast_sigmoid(float x) {
    return 1.0f / (1.0f + __expf(-x));
}
__device__ __forceinline__ float fast_tanh(float x) {
    return 2.0f / (1.0f + __expf(-2.0f*x)) - 1.0f;
}

// ---------------------------------------------------------------------------
// Kernel A: Wx = x @ gat_W, stored transposed per bt as [72][512] (tf32-rounded;
// row 64 = ones for the softmax denominator, rows 65..71 zero), plus per-node
// exp factors. grid 2048 = bt(256) x jchunk(8); block 256.
// ---------------------------------------------------------------------------
__global__ __launch_bounds__(256) void gat_proj_kernel(const float* __restrict__ x,
                                const float* __restrict__ W,
                                const float* __restrict__ attS,
                                const float* __restrict__ attD) {
    __shared__ float Ws[Ff*Hh];
    __shared__ float aS[Hh], aD[Hh];
    __shared__ float WxS[64][68];
    int tid = threadIdx.x;
    int bt = blockIdx.x >> 3;
    int j0 = (blockIdx.x & 7) * 64;
    if (tid < 256) Ws[tid] = W[tid];
    if (tid < 64)  aS[tid] = attS[tid];
    else if (tid < 128) aD[tid-64] = attD[tid-64];
    __syncthreads();

    int jj = tid >> 2, part = tid & 3;
    int node = bt*Nn + j0 + jj;
    float4 xv = *(const float4*)(x + (size_t)node*4);
    float vs = 0.f, vd = 0.f;
    #pragma unroll
    for (int k = 0; k < 16; k++) {
        int h = part*16 + k;
        float wx = xv.x*Ws[h] + xv.y*Ws[64+h] + xv.z*Ws[128+h] + xv.w*Ws[192+h];
        WxS[jj][h] = wx;
        vs = fmaf(wx, aS[h], vs);
        vd = fmaf(wx, aD[h], vd);
    }
    vs += __shfl_down_sync(0xffffffffu, vs, 2);
    vs += __shfl_down_sync(0xffffffffu, vs, 1);
    vd += __shfl_down_sync(0xffffffffu, vd, 2);
    vd += __shfl_down_sync(0xffffffffu, vd, 1);
    if (part == 0)
        g_Esc[node] = make_float4(expf(vs), expf(0.2f*vs), expf(vd), expf(0.2f*vd));
    __syncthreads();

    // transposed, tf32-rounded write
    int h = tid >> 2, q = tid & 3;
    float* dst = g_WxT + ((size_t)bt*NA + h)*Nn + j0 + q*16;
    #pragma unroll
    for (int v = 0; v < 4; v++) {
        uint4 f;
        f.x = cvt_tf32(WxS[q*16+v*4+0][h]);
        f.y = cvt_tf32(WxS[q*16+v*4+1][h]);
        f.z = cvt_tf32(WxS[q*16+v*4+2][h]);
        f.w = cvt_tf32(WxS[q*16+v*4+3][h]);
        *(uint4*)(dst + v*4) = f;
    }
    // augmentation rows 64..71
    if (tid < 128) {
        int r = tid >> 4, jq = tid & 15;
        float val = (r == 0) ? 1.0f : 0.0f;
        *(float4*)(g_WxT + ((size_t)bt*NA + 64 + r)*Nn + j0 + jq*4) =
            make_float4(val, val, val, val);
    }
}

// ---------------------------------------------------------------------------
// Kernel B: attention aggregate via mma.sync tf32 (m16n8k8).
// grid (4 i-tiles, 256 bt); 128 threads = 4 warps x 32 i-rows.
// ---------------------------------------------------------------------------
__global__ __launch_bounds__(128, 3)
void gat_attn_mma(const float* __restrict__ adj, const float* __restrict__ bias) {
    __shared__ float smB[NA*36];        // [h][36] : 10.4 KB
    __shared__ float E1sS[32], E2sS[32];
    __shared__ float biasS[64];

    int bt = blockIdx.y;
    int i0 = blockIdx.x * 128;
    int tid = threadIdx.x, wid = tid >> 5, lane = tid & 31;
    int lr = lane >> 2, lc = lane & 3;
    int ibase = i0 + wid*32;            // this warp's first i row (within bt)

    if (tid < 64) biasS[tid] = bias[tid];

    float e1d[4], e2d[4];
    #pragma unroll
    for (int m = 0; m < 4; m++) {
        float4 e = g_Esc[bt*Nn + ibase + lr + 8*m];
        e1d[m] = e.z; e2d[m] = e.w;
    }

    float acc[2][9][4];
    #pragma unroll
    for (int f = 0; f < 2; f++)
        #pragma unroll
        for (int nf = 0; nf < 9; nf++)
            #pragma unroll
            for (int r = 0; r < 4; r++) acc[f][nf][r] = 0.0f;

    const float* adjbt = adj + (size_t)bt*Nn*Nn;
    const float* WxTbt = g_WxT + (size_t)bt*NA*Nn;

    for (int c = 0; c < 16; c++) {
        int j0 = c * 32;
        // 1) adj gmem loads
        float av[4][8];
        #pragma unroll
        for (int ks = 0; ks < 4; ks++) {
            const float* r1 = adjbt + (size_t)(j0 + 8*ks + lc)*Nn + ibase + lr;
            const float* r2 = r1 + 4*Nn;
            #pragma unroll
            for (int f = 0; f < 2; f++) {
                av[ks][f*4+0] = r1[16*f];
                av[ks][f*4+1] = r1[16*f + 8];
                av[ks][f*4+2] = r2[16*f];
                av[ks][f*4+3] = r2[16*f + 8];
            }
        }
        __syncthreads();
        // 3) stage B tile [72 h][32 j] (stride 36) + exp factors
        #pragma unroll
        for (int t = 0; t < 5; t++) {
            int idx = tid + t*128;
            if (idx < 576) {
                int h = idx >> 3, q = idx & 7;
                float4 v = *(const float4*)(WxTbt + (size_t)h*Nn + j0 + q*4);
                *(float4*)(smB + h*36 + q*4) = v;
            }
        }
        if (tid < 32) {
            float4 e = g_Esc[bt*Nn + j0 + tid];
            E1sS[tid] = e.x; E2sS[tid] = e.y;
        }
        __syncthreads();

        // 4) per K=8 step: build A fragments in regs, LDS B frags, MMA
        #pragma unroll
        for (int ks = 0; ks < 4; ks++) {
            int jl = 8*ks + lc;
            float E1a = E1sS[jl],   E2a = E2sS[jl];
            float E1b = E1sS[jl+4], E2b = E2sS[jl+4];
            uint32_t A[2][4];
            #pragma unroll
            for (int f = 0; f < 2; f++) {
                #pragma unroll
                for (int t = 0; t < 4; t++) {
                    int m = 2*f + (t & 1);
                    float E1 = (t < 2) ? E1a : E1b;
                    float E2 = (t < 2) ? E2a : E2b;
                    float a  = av[ks][f*4+t];
                    float p1 = e1d[m] * E1;
                    float w  = (p1 > 1.0f) ? p1 : e2d[m] * E2;
                    int ig = ibase + lr + 16*f + 8*(t & 1);
                    int jg = j0 + jl + ((t < 2) ? 0 : 4);
                    w = ((a != 0.0f) || (ig == jg)) ? w : 0.0f;
                    A[f][t] = cvt_tf32(w);
                }
            }
            #pragma unroll
            for (int nf = 0; nf < 9; nf++) {
                uint32_t b0 = __float_as_uint(smB[(lr + 8*nf)*36 + jl]);
                uint32_t b1 = __float_as_uint(smB[(lr + 8*nf)*36 + jl + 4]);
                mma_tf32(acc[0][nf], A[0], b0, b1);
                mma_tf32(acc[1][nf], A[1], b0, b1);
            }
        }
    }

    // epilogue
    const unsigned FULL = 0xffffffffu;
    float inv[4];
    {
        int src = lane & 28;
        float d0 = __shfl_sync(FULL, acc[0][8][0], src);
        float d1 = __shfl_sync(FULL, acc[0][8][2], src);
        float d2 = __shfl_sync(FULL, acc[1][8][0], src);
        float d3 = __shfl_sync(FULL, acc[1][8][2], src);
        inv[0] = 1.0f/d0; inv[1] = 1.0f/d1; inv[2] = 1.0f/d2; inv[3] = 1.0f/d3;
    }
    #pragma unroll
    for (int f = 0; f < 2; f++) {
        #pragma unroll
        for (int nf = 0; nf < 8; nf++) {
            int col = 8*nf + 2*lc;
            float b0 = biasS[col], b1 = biasS[col+1];
            int rowA = ibase + lr + 16*f;
            float2 v0 = make_float2(acc[f][nf][0]*inv[2*f]   + b0,
                                    acc[f][nf][1]*inv[2*f]   + b1);
            float2 v1 = make_float2(acc[f][nf][2]*inv[2*f+1] + b0,
                                    acc[f][nf][3]*inv[2*f+1] + b1);
            *(float2*)(g_gat + (size_t)(bt*Nn + rowA)*64 + col)     = v0;
            *(float2*)(g_gat + (size_t)(bt*Nn + rowA + 8)*64 + col) = v1;
        }
    }
}

// ---------------------------------------------------------------------------
// Kernel C1 (NEW): gates_x = seq @ W_ih^T + b_ih via tf32 mma.sync.
// C[row, g] = sum_h gat[row, h] * Wih[g, h],  N padded 12 -> 16 (2 n-frags).
// Weights held entirely in 32 registers per thread; A-frags straight from gmem
// (no smem => no bank conflicts). Bias folded into accumulator init.
// grid 1024 x 128 threads; warp = 32 rows.
// ---------------------------------------------------------------------------
__global__ __launch_bounds__(128)
void gru_gates_mma(const float* __restrict__ Wih, const float* __restrict__ bih) {
    int tid = threadIdx.x, wid = tid >> 5, lane = tid & 31;
    int lr = lane >> 2, lc = lane & 3;
    size_t row0 = (size_t)blockIdx.x*128 + wid*32;

    // B fragments: Bv[ks][nf][r];  B[k][n] = Wih[n][k] (col-major B operand)
    uint32_t Bv[8][2][2];
    #pragma unroll
    for (int ks = 0; ks < 8; ks++)
        #pragma unroll
        for (int nf = 0; nf < 2; nf++) {
            int g = nf*8 + lr;
            if (g < 12) {
                const float* wp = Wih + g*64 + ks*8 + lc;
                Bv[ks][nf][0] = cvt_tf32(__ldg(wp));
                Bv[ks][nf][1] = cvt_tf32(__ldg(wp + 4));
            } else {
                Bv[ks][nf][0] = 0u; Bv[ks][nf][1] = 0u;
            }
        }

    float acc[2][2][4];
    #pragma unroll
    for (int ms = 0; ms < 2; ms++)
        #pragma unroll
        for (int nf = 0; nf < 2; nf++) {
            int col = nf*8 + 2*lc;
            float b0 = (col < 12)  ? __ldg(bih + col)     : 0.0f;
            float b1 = (col+1 < 12)? __ldg(bih + col + 1) : 0.0f;
            acc[ms][nf][0] = b0; acc[ms][nf][1] = b1;
            acc[ms][nf][2] = b0; acc[ms][nf][3] = b1;
        }

    #pragma unroll
    for (int ks = 0; ks < 8; ks++) {
        #pragma unroll
        for (int ms = 0; ms < 2; ms++) {
            const float* ap = g_gat + (row0 + ms*16 + lr)*64 + ks*8 + lc;
            uint32_t A[4];
            A[0] = cvt_tf32(ap[0]);
            A[1] = cvt_tf32(ap[8*64]);
            A[2] = cvt_tf32(ap[4]);
            A[3] = cvt_tf32(ap[8*64 + 4]);
            mma_tf32(acc[ms][0], A, Bv[ks][0][0], Bv[ks][0][1]);
            mma_tf32(acc[ms][1], A, Bv[ks][1][0], Bv[ks][1][1]);
        }
    }

    #pragma unroll
    for (int ms = 0; ms < 2; ms++)
        #pragma unroll
        for (int nf = 0; nf < 2; nf++) {
            int col = nf*8 + 2*lc;
            if (col < 12) {     // valid pairs: 0,2,4,6,8,10 (col 12,14 dropped)
                size_t r = row0 + ms*16 + lr;
                *(float2*)(g_gatesx + r*12 + col) =
                    make_float2(acc[ms][nf][0], acc[ms][nf][1]);
                *(float2*)(g_gatesx + (r+8)*12 + col) =
                    make_float2(acc[ms][nf][2], acc[ms][nf][3]);
            }
        }
}

// ---------------------------------------------------------------------------
// Kernel C2: GRU recurrence, hidden=4, T=8. One thread per sequence.
// ---------------------------------------------------------------------------
__global__ void gru_scan_kernel(const float* __restrict__ Whh,
                                const float* __restrict__ bhh) {
    __shared__ float WS[48], bS[12];
    int tid = threadIdx.x;
    if (tid < 48) WS[tid] = Whh[tid];
    if (tid < 12) bS[tid] = bhh[tid];
    __syncthreads();

    int s = blockIdx.x*blockDim.x + tid;   // 0..16383
    float h[4] = {0.f, 0.f, 0.f, 0.f};
    for (int t = 0; t < Tt; t++) {
        const float* gx = g_gatesx + (size_t)(s*Tt + t)*12;
        float4 g0 = *(const float4*)(gx);
        float4 g1 = *(const float4*)(gx + 4);
        float4 g2 = *(const float4*)(gx + 8);
        float gxa[12] = {g0.x,g0.y,g0.z,g0.w, g1.x,g1.y,g1.z,g1.w, g2.x,g2.y,g2.z,g2.w};
        float hh[12];
        #pragma unroll
        for (int g = 0; g < 12; g++)
            hh[g] = bS[g] + WS[g*4]*h[0] + WS[g*4+1]*h[1] + WS[g*4+2]*h[2] + WS[g*4+3]*h[3];
        #pragma unroll
        for (int f = 0; f < 4; f++) {
            float r = fast_sigmoid(gxa[f]   + hh[f]);
            float z = fast_sigmoid(gxa[4+f] + hh[4+f]);
            float nc = fast_tanh(gxa[8+f] + r*hh[8+f]);
            h[f] = (1.0f - z)*nc + z*h[f];
        }
        *(float4*)(g_gru + (size_t)(s*Tt + t)*4) = make_float4(h[0],h[1],h[2],h[3]);
    }
}

// ---------------------------------------------------------------------------
// Kernel D: Conv2d(8 -> 12, 3x3, pad 1) over (N, 4) fused with Linear(4 -> 2)
// ---------------------------------------------------------------------------
__global__ void conv_out_kernel(const float* __restrict__ convW,
                                const float* __restrict__ convb,
                                const float* __restrict__ outW,
                                const float* __restrict__ outb,
                                float* __restrict__ out) {
    __shared__ float cw[CO*Tt*9];
    __shared__ float cb[CO], ow[8], ob[2];
    int tid = threadIdx.x;
    for (int k = tid; k < CO*Tt*9; k += 256) cw[k] = convW[k];
    if (tid < CO) cb[tid] = convb[tid];
    if (tid < 8)  ow[tid] = outW[tid];
    if (tid < 2)  ob[tid] = outb[tid];
    __syncthreads();

    int idx = blockIdx.x*256 + tid;
    int n  = idx & 511;
    int co = (idx >> 9) % CO;
    int b  = idx / (512*CO);

    float y0 = cb[co], y1 = y0, y2 = y0, y3 = y0;
    #pragma unroll
    for (int kh = 0; kh < 3; kh++) {
        int nn = n + kh - 1;
        if (nn < 0 || nn >= Nn) continue;
        const float* gbase = g_gru + (size_t)(b*Nn + nn)*(Tt*Ff);
        #pragma unroll
        for (int ci = 0; ci < Tt; ci++) {
            float4 gv = *(const float4*)(gbase + ci*4);
            const float* wk = cw + ((co*Tt + ci)*3 + kh)*3;
            float w0 = wk[0], w1 = wk[1], w2 = wk[2];
            y1 = fmaf(w0, gv.x, y1); y2 = fmaf(w0, gv.y, y2); y3 = fmaf(w0, gv.z, y3);
            y0 = fmaf(w1, gv.x, y0); y1 = fmaf(w1, gv.y, y1);
            y2 = fmaf(w1, gv.z, y2); y3 = fmaf(w1, gv.w, y3);
            y0 = fmaf(w2, gv.y, y0); y1 = fmaf(w2, gv.z, y1); y2 = fmaf(w2, gv.w, y2);
        }
    }
    float o0 = ob[0] + y0*ow[0] + y1*ow[1] + y2*ow[2] + y3*ow[3];
    float o1 = ob[1] + y0*ow[4] + y1*ow[5] + y2*ow[6] + y3*ow[7];
    ((float2*)out)[idx] = make_float2(o0, o1);
}

// ---------------------------------------------------------------------------
extern "C" void kernel_launch(void* const* d_in, const int* in_sizes, int n_in,
                              void* d_out, int out_size) {
    const float* x        = (const float*)d_in[0];
    const float* adj      = (const float*)d_in[1];
    const float* gat_W    = (const float*)d_in[2];
    const float* att_src  = (const float*)d_in[3];
    const float* att_dst  = (const float*)d_in[4];
    const float* gat_bias = (const float*)d_in[5];
    const float* gru_Wih  = (const float*)d_in[6];
    const float* gru_Whh  = (const float*)d_in[7];
    const float* gru_bih  = (const float*)d_in[8];
    const float* gru_bhh  = (const float*)d_in[9];
    const float* conv_W   = (const float*)d_in[10];
    const float* conv_b   = (const float*)d_in[11];
    const float* out_W    = (const float*)d_in[12];
    const float* out_b    = (const float*)d_in[13];
    float* out = (float*)d_out;

    gat_proj_kernel<<<2048, 256>>>(x, gat_W, att_src, att_dst);
    gat_attn_mma<<<dim3(4, Bb*Tt), 128>>>(adj, gat_bias);
    gru_gates_mma<<<NODES/128, 128>>>(gru_Wih, gru_bih);
    gru_scan_kernel<<<256, 64>>>(gru_Whh, gru_bhh);
    conv_out_kernel<<<(Bb*CO*Nn)/256, 256>>>(conv_W, conv_b, out_W, out_b, out);
}

// round 5
// speedup vs baseline: 5.1912x; 1.7128x over previous
#include <cuda_runtime.h>
#include <math.h>
#include <cstdint>

// Shapes
#define Bb 32
#define Tt 8
#define Nn 512
#define Ff 4
#define Hh 64
#define CO 12
#define NZ 16                       // 12 gate cols + 1 ones col (den) + 3 pad
#define NODES (Bb*Tt*Nn)            // 131072
#define SEQS  (Bb*Nn)               // 16384

// Scratch (device globals)
__device__ float  g_M[48];                      // gat_W @ Wih^T  [f][12]
__device__ float  g_vs4[4], g_vd4[4];           // gat_W @ att_{src,dst}
__device__ float  g_cS[12];                     // Wih @ gat_bias + bih
__device__ float  g_ZT[(size_t)Bb*Tt*NZ*Nn];    // [bt][16][512], tf32-rounded
__device__ float4 g_Esc[NODES];                 // {e^s, e^.2s, e^d, e^.2d}
__device__ float  g_gatesx[(size_t)NODES*12];
__device__ float  g_gru[(size_t)SEQS*Tt*Ff];

// ---------------- helpers ----------------
__device__ __forceinline__ uint32_t cvt_tf32(float x) {
    uint32_t r;
    asm("cvt.rna.tf32.f32 %0, %1;" : "=r"(r) : "f"(x));
    return r;
}
__device__ __forceinline__ void mma_tf32(float c[4], const uint32_t a[4],
                                         uint32_t b0, uint32_t b1) {
    asm volatile(
        "mma.sync.aligned.m16n8k8.row.col.f32.tf32.tf32.f32 "
        "{%0,%1,%2,%3}, {%4,%5,%6,%7}, {%8,%9}, {%0,%1,%2,%3};"
        : "+f"(c[0]), "+f"(c[1]), "+f"(c[2]), "+f"(c[3])
        : "r"(a[0]), "r"(a[1]), "r"(a[2]), "r"(a[3]), "r"(b0), "r"(b1));
}
__device__ __forceinline__ float fast_sigmoid(float x) {
    return 1.0f / (1.0f + __expf(-x));
}
__device__ __forceinline__ float fast_tanh(float x) {
    return 2.0f / (1.0f + __expf(-2.0f*x)) - 1.0f;
}

// ---------------------------------------------------------------------------
// Kernel P: tiny precompute of folded constant matrices.
// ---------------------------------------------------------------------------
__global__ void precompute_kernel(const float* __restrict__ gat_W,
                                  const float* __restrict__ attS,
                                  const float* __restrict__ attD,
                                  const float* __restrict__ Wih,
                                  const float* __restrict__ bih,
                                  const float* __restrict__ gat_bias) {
    int t = threadIdx.x;
    if (t < 48) {
        int f = t / 12, g = t % 12;
        float s = 0.f;
        for (int h = 0; h < Hh; h++) s = fmaf(gat_W[f*Hh + h], Wih[g*Hh + h], s);
        g_M[f*12 + g] = s;
    } else if (t < 52) {
        int f = t - 48;
        float s = 0.f;
        for (int h = 0; h < Hh; h++) s = fmaf(gat_W[f*Hh + h], attS[h], s);
        g_vs4[f] = s;
    } else if (t < 56) {
        int f = t - 52;
        float s = 0.f;
        for (int h = 0; h < Hh; h++) s = fmaf(gat_W[f*Hh + h], attD[h], s);
        g_vd4[f] = s;
    } else if (t < 68) {
        int g = t - 56;
        float s = bih[g];
        for (int h = 0; h < Hh; h++) s = fmaf(Wih[g*Hh + h], gat_bias[h], s);
        g_cS[g] = s;
    }
}

// ---------------------------------------------------------------------------
// Kernel A: per-node Z = x @ M (transposed store, tf32) + exp factors.
// grid 512 x 256 threads; node = blk*256+tid (2 blocks per bt).
// ---------------------------------------------------------------------------
__global__ __launch_bounds__(256) void gat_proj_kernel(const float* __restrict__ x) {
    __shared__ float Ms[48], vsS[4], vdS[4];
    int tid = threadIdx.x;
    if (tid < 48) Ms[tid] = g_M[tid];
    else if (tid < 52) vsS[tid-48] = g_vs4[tid-48];
    else if (tid < 56) vdS[tid-52] = g_vd4[tid-52];
    __syncthreads();

    int node = blockIdx.x*256 + tid;
    int bt = node >> 9, j = node & 511;
    float4 xv = *(const float4*)(x + (size_t)node*4);

    float as = xv.x*vsS[0] + xv.y*vsS[1] + xv.z*vsS[2] + xv.w*vsS[3];
    float ad = xv.x*vdS[0] + xv.y*vdS[1] + xv.z*vdS[2] + xv.w*vdS[3];
    g_Esc[node] = make_float4(expf(as), expf(0.2f*as), expf(ad), expf(0.2f*ad));

    float* zt = g_ZT + (size_t)bt*NZ*Nn + j;
    #pragma unroll
    for (int g = 0; g < 12; g++) {
        float z = xv.x*Ms[g] + xv.y*Ms[12+g] + xv.z*Ms[24+g] + xv.w*Ms[36+g];
        zt[(size_t)g*Nn] = __uint_as_float(cvt_tf32(z));
    }
    zt[12*Nn] = 1.0f;
    zt[13*Nn] = 0.0f; zt[14*Nn] = 0.0f; zt[15*Nn] = 0.0f;
}

// ---------------------------------------------------------------------------
// Kernel B: attention-normalized gates via mma.sync tf32 (m16n8k8), N=16.
// gates[i,g] = (sum_j w_ij * Z[j,g]) / (sum_j w_ij) + cS[g]
// grid (4 i-tiles, 256 bt); 128 threads = 4 warps x 32 i-rows.
// ---------------------------------------------------------------------------
__global__ __launch_bounds__(128)
void gat_attn_mma(const float* __restrict__ adj) {
    __shared__ float smB[NZ*36];        // [zc][36]
    __shared__ float E1sS[32], E2sS[32];
    __shared__ float cSs[12];

    int bt = blockIdx.y;
    int i0 = blockIdx.x * 128;
    int tid = threadIdx.x, wid = tid >> 5, lane = tid & 31;
    int lr = lane >> 2, lc = lane & 3;
    int ibase = i0 + wid*32;

    if (tid < 12) cSs[tid] = g_cS[tid];

    float e1d[4], e2d[4];
    #pragma unroll
    for (int m = 0; m < 4; m++) {
        float4 e = g_Esc[bt*Nn + ibase + lr + 8*m];
        e1d[m] = e.z; e2d[m] = e.w;
    }

    float acc[2][2][4];
    #pragma unroll
    for (int f = 0; f < 2; f++)
        #pragma unroll
        for (int nf = 0; nf < 2; nf++)
            #pragma unroll
            for (int r = 0; r < 4; r++) acc[f][nf][r] = 0.0f;

    const float* adjbt = adj + (size_t)bt*Nn*Nn;
    const float* ZTbt  = g_ZT + (size_t)bt*NZ*Nn;

    for (int c = 0; c < 16; c++) {
        int j0 = c * 32;
        // 1) adj gmem loads (full-sector pattern)
        float av[4][8];
        #pragma unroll
        for (int ks = 0; ks < 4; ks++) {
            const float* r1 = adjbt + (size_t)(j0 + 8*ks + lc)*Nn + ibase + lr;
            const float* r2 = r1 + 4*Nn;
            #pragma unroll
            for (int f = 0; f < 2; f++) {
                av[ks][f*4+0] = r1[16*f];
                av[ks][f*4+1] = r1[16*f + 8];
                av[ks][f*4+2] = r2[16*f];
                av[ks][f*4+3] = r2[16*f + 8];
            }
        }
        __syncthreads();
        // 2) stage B tile [16 zc][32 j] (stride 36) + exp factors
        if (tid < 128) {
            int h = tid >> 3, q = tid & 7;
            float4 v = *(const float4*)(ZTbt + (size_t)h*Nn + j0 + q*4);
            *(float4*)(smB + h*36 + q*4) = v;
        }
        if (tid < 32) {
            float4 e = g_Esc[bt*Nn + j0 + tid];
            E1sS[tid] = e.x; E2sS[tid] = e.y;
        }
        __syncthreads();

        // 3) per K=8 step: build A fragments in regs, LDS B frags, MMA
        #pragma unroll
        for (int ks = 0; ks < 4; ks++) {
            int jl = 8*ks + lc;
            float E1a = E1sS[jl],   E2a = E2sS[jl];
            float E1b = E1sS[jl+4], E2b = E2sS[jl+4];
            uint32_t A[2][4];
            #pragma unroll
            for (int f = 0; f < 2; f++) {
                #pragma unroll
                for (int t = 0; t < 4; t++) {
                    int m = 2*f + (t & 1);
                    float E1 = (t < 2) ? E1a : E1b;
                    float E2 = (t < 2) ? E2a : E2b;
                    float a  = av[ks][f*4+t];
                    float p1 = e1d[m] * E1;
                    float w  = (p1 > 1.0f) ? p1 : e2d[m] * E2;
                    int ig = ibase + lr + 16*f + 8*(t & 1);
                    int jg = j0 + jl + ((t < 2) ? 0 : 4);
                    w = ((a != 0.0f) || (ig == jg)) ? w : 0.0f;
                    A[f][t] = cvt_tf32(w);
                }
            }
            #pragma unroll
            for (int nf = 0; nf < 2; nf++) {
                uint32_t b0 = __float_as_uint(smB[(lr + 8*nf)*36 + jl]);
                uint32_t b1 = __float_as_uint(smB[(lr + 8*nf)*36 + jl + 4]);
                mma_tf32(acc[0][nf], A[0], b0, b1);
                mma_tf32(acc[1][nf], A[1], b0, b1);
            }
        }
    }

    // epilogue: denominator = accumulator col 12 -> nf=1, lanes lc==2
    const unsigned FULL = 0xffffffffu;
    float inv[4];
    {
        int src = (lane & 28) | 2;
        float d0 = __shfl_sync(FULL, acc[0][1][0], src);
        float d1 = __shfl_sync(FULL, acc[0][1][2], src);
        float d2 = __shfl_sync(FULL, acc[1][1][0], src);
        float d3 = __shfl_sync(FULL, acc[1][1][2], src);
        inv[0] = 1.0f/d0; inv[1] = 1.0f/d1; inv[2] = 1.0f/d2; inv[3] = 1.0f/d3;
    }
    #pragma unroll
    for (int f = 0; f < 2; f++) {
        #pragma unroll
        for (int nf = 0; nf < 2; nf++) {
            int col = 8*nf + 2*lc;
            if (col + 1 < 12) {
                float b0 = cSs[col], b1 = cSs[col+1];
                size_t rowA = (size_t)bt*Nn + ibase + lr + 16*f;
                float2 v0 = make_float2(acc[f][nf][0]*inv[2*f]   + b0,
                                        acc[f][nf][1]*inv[2*f]   + b1);
                float2 v1 = make_float2(acc[f][nf][2]*inv[2*f+1] + b0,
                                        acc[f][nf][3]*inv[2*f+1] + b1);
                *(float2*)(g_gatesx + rowA*12 + col)     = v0;
                *(float2*)(g_gatesx + (rowA+8)*12 + col) = v1;
            }
        }
    }
}

// ---------------------------------------------------------------------------
// Kernel C: GRU recurrence, hidden=4, T=8. FOUR threads per sequence,
// h exchanged via shfl within aligned quads; gx prefetched one step ahead.
// ---------------------------------------------------------------------------
__global__ __launch_bounds__(256) void gru_scan_kernel(const float* __restrict__ Whh,
                                const float* __restrict__ bhh) {
    __shared__ float WS[48], bS[12];
    int tid = threadIdx.x;
    if (tid < 48) WS[tid] = Whh[tid];
    if (tid < 12) bS[tid] = bhh[tid];
    __syncthreads();

    int gidx = blockIdx.x*256 + tid;       // 65536
    int s = gidx >> 2, f = gidx & 3;
    int lane = tid & 31, base = lane & ~3;

    float Wr[4], Wz[4], Wn[4];
    #pragma unroll
    for (int k = 0; k < 4; k++) {
        Wr[k] = WS[f*4 + k];
        Wz[k] = WS[(4+f)*4 + k];
        Wn[k] = WS[(8+f)*4 + k];
    }
    float br = bS[f], bz = bS[4+f], bn = bS[8+f];

    const float* gx = g_gatesx + (size_t)s*(Tt*12) + f;
    float p0 = gx[0], p1 = gx[4], p2 = gx[8];

    const unsigned FULL = 0xffffffffu;
    float h = 0.0f;
    #pragma unroll
    for (int t = 0; t < Tt; t++) {
        float c0 = p0, c1 = p1, c2 = p2;
        if (t < Tt-1) {
            p0 = gx[(t+1)*12];
            p1 = gx[(t+1)*12 + 4];
            p2 = gx[(t+1)*12 + 8];
        }
        float h0 = __shfl_sync(FULL, h, base);
        float h1 = __shfl_sync(FULL, h, base+1);
        float h2 = __shfl_sync(FULL, h, base+2);
        float h3 = __shfl_sync(FULL, h, base+3);
        float hr = br + Wr[0]*h0 + Wr[1]*h1 + Wr[2]*h2 + Wr[3]*h3;
        float hz = bz + Wz[0]*h0 + Wz[1]*h1 + Wz[2]*h2 + Wz[3]*h3;
        float hn = bn + Wn[0]*h0 + Wn[1]*h1 + Wn[2]*h2 + Wn[3]*h3;
        float r  = fast_sigmoid(c0 + hr);
        float z  = fast_sigmoid(c1 + hz);
        float nc = fast_tanh(c2 + r*hn);
        h = (1.0f - z)*nc + z*h;
        g_gru[((size_t)s*Tt + t)*4 + f] = h;
    }
}

// ---------------------------------------------------------------------------
// Kernel D: Conv2d(8 -> 12, 3x3, pad 1) over (N, 4) fused with Linear(4 -> 2)
// ---------------------------------------------------------------------------
__global__ void conv_out_kernel(const float* __restrict__ convW,
                                const float* __restrict__ convb,
                                const float* __restrict__ outW,
                                const float* __restrict__ outb,
                                float* __restrict__ out) {
    __shared__ float cw[CO*Tt*9];
    __shared__ float cb[CO], ow[8], ob[2];
    int tid = threadIdx.x;
    for (int k = tid; k < CO*Tt*9; k += 256) cw[k] = convW[k];
    if (tid < CO) cb[tid] = convb[tid];
    if (tid < 8)  ow[tid] = outW[tid];
    if (tid < 2)  ob[tid] = outb[tid];
    __syncthreads();

    int idx = blockIdx.x*256 + tid;
    int n  = idx & 511;
    int co = (idx >> 9) % CO;
    int b  = idx / (512*CO);

    float y0 = cb[co], y1 = y0, y2 = y0, y3 = y0;
    #pragma unroll
    for (int kh = 0; kh < 3; kh++) {
        int nn = n + kh - 1;
        if (nn < 0 || nn >= Nn) continue;
        const float* gbase = g_gru + (size_t)(b*Nn + nn)*(Tt*Ff);
        #pragma unroll
        for (int ci = 0; ci < Tt; ci++) {
            float4 gv = *(const float4*)(gbase + ci*4);
            const float* wk = cw + ((co*Tt + ci)*3 + kh)*3;
            float w0 = wk[0], w1 = wk[1], w2 = wk[2];
            y1 = fmaf(w0, gv.x, y1); y2 = fmaf(w0, gv.y, y2); y3 = fmaf(w0, gv.z, y3);
            y0 = fmaf(w1, gv.x, y0); y1 = fmaf(w1, gv.y, y1);
            y2 = fmaf(w1, gv.z, y2); y3 = fmaf(w1, gv.w, y3);
            y0 = fmaf(w2, gv.y, y0); y1 = fmaf(w2, gv.z, y1); y2 = fmaf(w2, gv.w, y2);
        }
    }
    float o0 = ob[0] + y0*ow[0] + y1*ow[1] + y2*ow[2] + y3*ow[3];
    float o1 = ob[1] + y0*ow[4] + y1*ow[5] + y2*ow[6] + y3*ow[7];
    ((float2*)out)[idx] = make_float2(o0, o1);
}

// ---------------------------------------------------------------------------
extern "C" void kernel_launch(void* const* d_in, const int* in_sizes, int n_in,
                              void* d_out, int out_size) {
    const float* x        = (const float*)d_in[0];
    const float* adj      = (const float*)d_in[1];
    const float* gat_W    = (const float*)d_in[2];
    const float* att_src  = (const float*)d_in[3];
    const float* att_dst  = (const float*)d_in[4];
    const float* gat_bias = (const float*)d_in[5];
    const float* gru_Wih  = (const float*)d_in[6];
    const float* gru_Whh  = (const float*)d_in[7];
    const float* gru_bih  = (const float*)d_in[8];
    const float* gru_bhh  = (const float*)d_in[9];
    const float* conv_W   = (const float*)d_in[10];
    const float* conv_b   = (const float*)d_in[11];
    const float* out_W    = (const float*)d_in[12];
    const float* out_b    = (const float*)d_in[13];
    float* out = (float*)d_out;

    precompute_kernel<<<1, 128>>>(gat_W, att_src, att_dst, gru_Wih, gru_bih, gat_bias);
    gat_proj_kernel<<<NODES/256, 256>>>(x);
    gat_attn_mma<<<dim3(4, Bb*Tt), 128>>>(adj);
    gru_scan_kernel<<<SEQS*4/256, 256>>>(gru_Whh, gru_bhh);
    conv_out_kernel<<<(Bb*CO*Nn)/256, 256>>>(conv_W, conv_b, out_W, out_b, out);
}

// round 6
// speedup vs baseline: 5.2923x; 1.0195x over previous
#include <cuda_runtime.h>
#include <math.h>
#include <cstdint>

// Shapes
#define Bb 32
#define Tt 8
#define Nn 512
#define Ff 4
#define Hh 64
#define CO 12
#define NZ 16
#define ZP 516                      // padded row stride (== 4 mod 32)
#define NODES (Bb*Tt*Nn)
#define SEQS  (Bb*Nn)

// Scratch (device globals)
__device__ float g_M[48];                      // gat_W @ Wih^T  [f][12]
__device__ float g_vs4[4], g_vd4[4];           // gat_W @ att_{src,dst}
__device__ float g_cS[12];                     // Wih @ gat_bias + bih
__device__ float g_gatesx[(size_t)NODES*12];
__device__ float g_gru[(size_t)SEQS*Tt*Ff];

// ---------------- helpers ----------------
__device__ __forceinline__ uint32_t cvt_tf32(float x) {
    uint32_t r;
    asm("cvt.rna.tf32.f32 %0, %1;" : "=r"(r) : "f"(x));
    return r;
}
__device__ __forceinline__ void mma_tf32(float c[4], const uint32_t a[4],
                                         uint32_t b0, uint32_t b1) {
    asm volatile(
        "mma.sync.aligned.m16n8k8.row.col.f32.tf32.tf32.f32 "
        "{%0,%1,%2,%3}, {%4,%5,%6,%7}, {%8,%9}, {%0,%1,%2,%3};"
        : "+f"(c[0]), "+f"(c[1]), "+f"(c[2]), "+f"(c[3])
        : "r"(a[0]), "r"(a[1]), "r"(a[2]), "r"(a[3]), "r"(b0), "r"(b1));
}
__device__ __forceinline__ float fast_sigmoid(float x) {
    return 1.0f / (1.0f + __expf(-x));
}
__device__ __forceinline__ float fast_tanh(float x) {
    return 2.0f / (1.0f + __expf(-2.0f*x)) - 1.0f;
}

// ---------------------------------------------------------------------------
// Kernel P: folded constants.
// ---------------------------------------------------------------------------
__global__ void precompute_kernel(const float* __restrict__ gat_W,
                                  const float* __restrict__ attS,
                                  const float* __restrict__ attD,
                                  const float* __restrict__ Wih,
                                  const float* __restrict__ bih,
                                  const float* __restrict__ gat_bias) {
    int t = threadIdx.x;
    if (t < 48) {
        int f = t / 12, g = t % 12;
        float s = 0.f;
        for (int h = 0; h < Hh; h++) s = fmaf(gat_W[f*Hh + h], Wih[g*Hh + h], s);
        g_M[f*12 + g] = s;
    } else if (t < 52) {
        int f = t - 48;
        float s = 0.f;
        for (int h = 0; h < Hh; h++) s = fmaf(gat_W[f*Hh + h], attS[h], s);
        g_vs4[f] = s;
    } else if (t < 56) {
        int f = t - 52;
        float s = 0.f;
        for (int h = 0; h < Hh; h++) s = fmaf(gat_W[f*Hh + h], attD[h], s);
        g_vd4[f] = s;
    } else if (t < 68) {
        int g = t - 56;
        float s = bih[g];
        for (int h = 0; h < Hh; h++) s = fmaf(Wih[g*Hh + h], gat_bias[h], s);
        g_cS[g] = s;
    }
}

// ---------------------------------------------------------------------------
// Kernel B (fused GAT): per CTA (i-tile 128, bt):
//  prologue: compute Z[16][512] (tf32) and exp factors for the whole bt into
//  SMEM; then a sync-free 16-chunk mainloop of adj-LDG -> w-frag -> tf32 MMA.
//  gates[i,g] = (sum_j w_ij Z[j,g]) / (sum_j w_ij) + cS[g]  -> g_gatesx
// ---------------------------------------------------------------------------
__global__ __launch_bounds__(128, 4)
void gat_fused(const float* __restrict__ x, const float* __restrict__ adj) {
    __shared__ float smB[NZ*ZP];                  // Z rows, stride 516
    __shared__ float E1s[Nn], E2s[Nn], E1d[Nn], E2d[Nn];
    __shared__ float Ms[48], vsS[4], vdS[4], cSs[12];

    int bt = blockIdx.y;
    int i0 = blockIdx.x * 128;
    int tid = threadIdx.x, wid = tid >> 5, lane = tid & 31;
    int lr = lane >> 2, lc = lane & 3;
    int ibase = i0 + wid*32;

    if (tid < 48) Ms[tid] = g_M[tid];
    else if (tid < 52) vsS[tid-48] = g_vs4[tid-48];
    else if (tid < 56) vdS[tid-52] = g_vd4[tid-52];
    else if (tid < 68) cSs[tid-56] = g_cS[tid-56];
    __syncthreads();

    // ---- prologue: Z + exp factors for all 512 j of this bt ----
    #pragma unroll
    for (int k = 0; k < 4; k++) {
        int j = tid + 128*k;
        float4 xv = __ldg((const float4*)(x + ((size_t)bt*Nn + j)*4));
        float as = xv.x*vsS[0] + xv.y*vsS[1] + xv.z*vsS[2] + xv.w*vsS[3];
        float ad = xv.x*vdS[0] + xv.y*vdS[1] + xv.z*vdS[2] + xv.w*vdS[3];
        E1s[j] = __expf(as); E2s[j] = __expf(0.2f*as);
        E1d[j] = __expf(ad); E2d[j] = __expf(0.2f*ad);
        #pragma unroll
        for (int g = 0; g < 12; g++) {
            float z = xv.x*Ms[g] + xv.y*Ms[12+g] + xv.z*Ms[24+g] + xv.w*Ms[36+g];
            smB[g*ZP + j] = __uint_as_float(cvt_tf32(z));
        }
        smB[12*ZP + j] = 1.0f;
        smB[13*ZP + j] = 0.0f;
        smB[14*ZP + j] = 0.0f;
        smB[15*ZP + j] = 0.0f;
    }
    __syncthreads();

    float e1d[4], e2d[4];
    #pragma unroll
    for (int m = 0; m < 4; m++) {
        int ii = ibase + lr + 8*m;
        e1d[m] = E1d[ii]; e2d[m] = E2d[ii];
    }

    float acc[2][2][4];
    #pragma unroll
    for (int f = 0; f < 2; f++)
        #pragma unroll
        for (int nf = 0; nf < 2; nf++)
            #pragma unroll
            for (int r = 0; r < 4; r++) acc[f][nf][r] = 0.0f;

    const float* adjbt = adj + (size_t)bt*Nn*Nn;

    // ---- sync-free mainloop ----
    #pragma unroll 2
    for (int c = 0; c < 16; c++) {
        int j0 = c * 32;
        float av[4][8];
        #pragma unroll
        for (int ks = 0; ks < 4; ks++) {
            const float* r1 = adjbt + (size_t)(j0 + 8*ks + lc)*Nn + ibase + lr;
            const float* r2 = r1 + 4*Nn;
            #pragma unroll
            for (int f = 0; f < 2; f++) {
                av[ks][f*4+0] = r1[16*f];
                av[ks][f*4+1] = r1[16*f + 8];
                av[ks][f*4+2] = r2[16*f];
                av[ks][f*4+3] = r2[16*f + 8];
            }
        }
        bool diagchunk = (j0 == ibase);   // warp-uniform

        #pragma unroll
        for (int ks = 0; ks < 4; ks++) {
            int jl = j0 + 8*ks + lc;
            float E1a = E1s[jl],   E2a = E2s[jl];
            float E1b = E1s[jl+4], E2b = E2s[jl+4];
            uint32_t A[2][4];
            if (diagchunk) {
                #pragma unroll
                for (int f = 0; f < 2; f++)
                    #pragma unroll
                    for (int t = 0; t < 4; t++) {
                        int m = 2*f + (t & 1);
                        float E1 = (t < 2) ? E1a : E1b;
                        float E2 = (t < 2) ? E2a : E2b;
                        float a  = av[ks][f*4+t];
                        float w  = fmaxf(e1d[m]*E1, e2d[m]*E2);
                        int ig = ibase + lr + 16*f + 8*(t & 1);
                        int jg = jl + ((t < 2) ? 0 : 4);
                        w = ((a != 0.0f) || (ig == jg)) ? w : 0.0f;
                        A[f][t] = __float_as_uint(w);
                    }
            } else {
                #pragma unroll
                for (int f = 0; f < 2; f++)
                    #pragma unroll
                    for (int t = 0; t < 4; t++) {
                        int m = 2*f + (t & 1);
                        float E1 = (t < 2) ? E1a : E1b;
                        float E2 = (t < 2) ? E2a : E2b;
                        float a  = av[ks][f*4+t];
                        float w  = fmaxf(e1d[m]*E1, e2d[m]*E2);
                        A[f][t] = (a != 0.0f) ? __float_as_uint(w) : 0u;
                    }
            }
            #pragma unroll
            for (int nf = 0; nf < 2; nf++) {
                uint32_t b0 = __float_as_uint(smB[(lr + 8*nf)*ZP + jl]);
                uint32_t b1 = __float_as_uint(smB[(lr + 8*nf)*ZP + jl + 4]);
                mma_tf32(acc[0][nf], A[0], b0, b1);
                mma_tf32(acc[1][nf], A[1], b0, b1);
            }
        }
    }

    // epilogue: denominator = col 12 -> acc[f][1] regs 0/2 at lanes lc==2
    const unsigned FULL = 0xffffffffu;
    float inv[4];
    {
        int src = (lane & 28) | 2;
        float d0 = __shfl_sync(FULL, acc[0][1][0], src);
        float d1 = __shfl_sync(FULL, acc[0][1][2], src);
        float d2 = __shfl_sync(FULL, acc[1][1][0], src);
        float d3 = __shfl_sync(FULL, acc[1][1][2], src);
        inv[0] = 1.0f/d0; inv[1] = 1.0f/d1; inv[2] = 1.0f/d2; inv[3] = 1.0f/d3;
    }
    #pragma unroll
    for (int f = 0; f < 2; f++) {
        #pragma unroll
        for (int nf = 0; nf < 2; nf++) {
            int col = 8*nf + 2*lc;
            if (col + 1 < 12) {
                float b0 = cSs[col], b1 = cSs[col+1];
                size_t rowA = (size_t)bt*Nn + ibase + lr + 16*f;
                float2 v0 = make_float2(acc[f][nf][0]*inv[2*f]   + b0,
                                        acc[f][nf][1]*inv[2*f]   + b1);
                float2 v1 = make_float2(acc[f][nf][2]*inv[2*f+1] + b0,
                                        acc[f][nf][3]*inv[2*f+1] + b1);
                *(float2*)(g_gatesx + rowA*12 + col)     = v0;
                *(float2*)(g_gatesx + (rowA+8)*12 + col) = v1;
            }
        }
    }
}

// ---------------------------------------------------------------------------
// Kernel C: GRU recurrence. Four threads per sequence; all gx loaded upfront.
// ---------------------------------------------------------------------------
__global__ __launch_bounds__(256) void gru_scan_kernel(const float* __restrict__ Whh,
                                const float* __restrict__ bhh) {
    __shared__ float WS[48], bS[12];
    int tid = threadIdx.x;
    if (tid < 48) WS[tid] = Whh[tid];
    if (tid < 12) bS[tid] = bhh[tid];
    __syncthreads();

    int gidx = blockIdx.x*256 + tid;
    int s = gidx >> 2, f = gidx & 3;
    int lane = tid & 31, base = lane & ~3;

    float Wr[4], Wz[4], Wn[4];
    #pragma unroll
    for (int k = 0; k < 4; k++) {
        Wr[k] = WS[f*4 + k];
        Wz[k] = WS[(4+f)*4 + k];
        Wn[k] = WS[(8+f)*4 + k];
    }
    float br = bS[f], bz = bS[4+f], bn = bS[8+f];

    const float* gx = g_gatesx + (size_t)s*(Tt*12) + f;
    float gv[24];
    #pragma unroll
    for (int t = 0; t < Tt; t++) {
        gv[3*t]   = gx[t*12];
        gv[3*t+1] = gx[t*12 + 4];
        gv[3*t+2] = gx[t*12 + 8];
    }

    const unsigned FULL = 0xffffffffu;
    float h = 0.0f;
    #pragma unroll
    for (int t = 0; t < Tt; t++) {
        float h0 = __shfl_sync(FULL, h, base);
        float h1 = __shfl_sync(FULL, h, base+1);
        float h2 = __shfl_sync(FULL, h, base+2);
        float h3 = __shfl_sync(FULL, h, base+3);
        float hr = br + Wr[0]*h0 + Wr[1]*h1 + Wr[2]*h2 + Wr[3]*h3;
        float hz = bz + Wz[0]*h0 + Wz[1]*h1 + Wz[2]*h2 + Wz[3]*h3;
        float hn = bn + Wn[0]*h0 + Wn[1]*h1 + Wn[2]*h2 + Wn[3]*h3;
        float r  = fast_sigmoid(gv[3*t]   + hr);
        float z  = fast_sigmoid(gv[3*t+1] + hz);
        float nc = fast_tanh(gv[3*t+2] + r*hn);
        h = (1.0f - z)*nc + z*h;
        g_gru[((size_t)s*Tt + t)*4 + f] = h;
    }
}

// ---------------------------------------------------------------------------
// Kernel D: Conv2d(8 -> 12, 3x3, pad 1) over (N, 4) fused with Linear(4 -> 2)
// ---------------------------------------------------------------------------
__global__ void conv_out_kernel(const float* __restrict__ convW,
                                const float* __restrict__ convb,
                                const float* __restrict__ outW,
                                const float* __restrict__ outb,
                                float* __restrict__ out) {
    __shared__ float cw[CO*Tt*9];
    __shared__ float cb[CO], ow[8], ob[2];
    int tid = threadIdx.x;
    for (int k = tid; k < CO*Tt*9; k += 256) cw[k] = convW[k];
    if (tid < CO) cb[tid] = convb[tid];
    if (tid < 8)  ow[tid] = outW[tid];
    if (tid < 2)  ob[tid] = outb[tid];
    __syncthreads();

    int idx = blockIdx.x*256 + tid;
    int n  = idx & 511;
    int co = (idx >> 9) % CO;
    int b  = idx / (512*CO);

    float y0 = cb[co], y1 = y0, y2 = y0, y3 = y0;
    #pragma unroll
    for (int kh = 0; kh < 3; kh++) {
        int nn = n + kh - 1;
        if (nn < 0 || nn >= Nn) continue;
        const float* gbase = g_gru + (size_t)(b*Nn + nn)*(Tt*Ff);
        #pragma unroll
        for (int ci = 0; ci < Tt; ci++) {
            float4 gv = *(const float4*)(gbase + ci*4);
            const float* wk = cw + ((co*Tt + ci)*3 + kh)*3;
            float w0 = wk[0], w1 = wk[1], w2 = wk[2];
            y1 = fmaf(w0, gv.x, y1); y2 = fmaf(w0, gv.y, y2); y3 = fmaf(w0, gv.z, y3);
            y0 = fmaf(w1, gv.x, y0); y1 = fmaf(w1, gv.y, y1);
            y2 = fmaf(w1, gv.z, y2); y3 = fmaf(w1, gv.w, y3);
            y0 = fmaf(w2, gv.y, y0); y1 = fmaf(w2, gv.z, y1); y2 = fmaf(w2, gv.w, y2);
        }
    }
    float o0 = ob[0] + y0*ow[0] + y1*ow[1] + y2*ow[2] + y3*ow[3];
    float o1 = ob[1] + y0*ow[4] + y1*ow[5] + y2*ow[6] + y3*ow[7];
    ((float2*)out)[idx] = make_float2(o0, o1);
}

// ---------------------------------------------------------------------------
extern "C" void kernel_launch(void* const* d_in, const int* in_sizes, int n_in,
                              void* d_out, int out_size) {
    const float* x        = (const float*)d_in[0];
    const float* adj      = (const float*)d_in[1];
    const float* gat_W    = (const float*)d_in[2];
    const float* att_src  = (const float*)d_in[3];
    const float* att_dst  = (const float*)d_in[4];
    const float* gat_bias = (const float*)d_in[5];
    const float* gru_Wih  = (const float*)d_in[6];
    const float* gru_Whh  = (const float*)d_in[7];
    const float* gru_bih  = (const float*)d_in[8];
    const float* gru_bhh  = (const float*)d_in[9];
    const float* conv_W   = (const float*)d_in[10];
    const float* conv_b   = (const float*)d_in[11];
    const float* out_W    = (const float*)d_in[12];
    const float* out_b    = (const float*)d_in[13];
    float* out = (float*)d_out;

    precompute_kernel<<<1, 128>>>(gat_W, att_src, att_dst, gru_Wih, gru_bih, gat_bias);
    gat_fused<<<dim3(4, Bb*Tt), 128>>>(x, adj);
    gru_scan_kernel<<<SEQS*4/256, 256>>>(gru_Whh, gru_bhh);
    conv_out_kernel<<<(Bb*CO*Nn)/256, 256>>>(conv_W, conv_b, out_W, out_b, out);
}

// round 7
// speedup vs baseline: 5.5842x; 1.0552x over previous
#include <cuda_runtime.h>
#include <math.h>
#include <cstdint>

// Shapes
#define Bb 32
#define Tt 8
#define Nn 512
#define Ff 4
#define Hh 64
#define CO 12
#define NZ 16
#define ZP 516                      // padded row stride (== 4 mod 32)
#define NODES (Bb*Tt*Nn)
#define SEQS  (Bb*Nn)

// Scratch (device globals)
__device__ float g_M[48];                      // gat_W @ Wih^T  [f][12]
__device__ float g_vs4[4], g_vd4[4];           // gat_W @ att_{src,dst}
__device__ float g_cS[12];                     // Wih @ gat_bias + bih
__device__ float g_gatesx[(size_t)NODES*12];
__device__ float g_gru[(size_t)Bb*Tt*Ff*Nn];   // layout [b][t][f][n]

// ---------------- helpers ----------------
__device__ __forceinline__ uint32_t cvt_tf32(float x) {
    uint32_t r;
    asm("cvt.rna.tf32.f32 %0, %1;" : "=r"(r) : "f"(x));
    return r;
}
__device__ __forceinline__ void mma_tf32(float c[4], const uint32_t a[4],
                                         uint32_t b0, uint32_t b1) {
    asm volatile(
        "mma.sync.aligned.m16n8k8.row.col.f32.tf32.tf32.f32 "
        "{%0,%1,%2,%3}, {%4,%5,%6,%7}, {%8,%9}, {%0,%1,%2,%3};"
        : "+f"(c[0]), "+f"(c[1]), "+f"(c[2]), "+f"(c[3])
        : "r"(a[0]), "r"(a[1]), "r"(a[2]), "r"(a[3]), "r"(b0), "r"(b1));
}
__device__ __forceinline__ float fast_sigmoid(float x) {
    return 1.0f / (1.0f + __expf(-x));
}
__device__ __forceinline__ float fast_tanh(float x) {
    return 2.0f / (1.0f + __expf(-2.0f*x)) - 1.0f;
}

// ---------------------------------------------------------------------------
// Kernel P: folded constants.
// ---------------------------------------------------------------------------
__global__ void precompute_kernel(const float* __restrict__ gat_W,
                                  const float* __restrict__ attS,
                                  const float* __restrict__ attD,
                                  const float* __restrict__ Wih,
                                  const float* __restrict__ bih,
                                  const float* __restrict__ gat_bias) {
    int t = threadIdx.x;
    if (t < 48) {
        int f = t / 12, g = t % 12;
        float s = 0.f;
        for (int h = 0; h < Hh; h++) s = fmaf(gat_W[f*Hh + h], Wih[g*Hh + h], s);
        g_M[f*12 + g] = s;
    } else if (t < 52) {
        int f = t - 48;
        float s = 0.f;
        for (int h = 0; h < Hh; h++) s = fmaf(gat_W[f*Hh + h], attS[h], s);
        g_vs4[f] = s;
    } else if (t < 56) {
        int f = t - 52;
        float s = 0.f;
        for (int h = 0; h < Hh; h++) s = fmaf(gat_W[f*Hh + h], attD[h], s);
        g_vd4[f] = s;
    } else if (t < 68) {
        int g = t - 56;
        float s = bih[g];
        for (int h = 0; h < Hh; h++) s = fmaf(Wih[g*Hh + h], gat_bias[h], s);
        g_cS[g] = s;
    }
}

// ---------------------------------------------------------------------------
// Kernel B (fused GAT): smB rows 0-11 = Z, row 12 = ones (denominator),
// rows 13/14 = E1s/E2s (pollute unread acc cols), row 15 = zero.
// 34.3KB smem -> 6 CTAs/SM.
// ---------------------------------------------------------------------------
__global__ __launch_bounds__(128, 6)
void gat_fused(const float* __restrict__ x, const float* __restrict__ adj) {
    __shared__ float smB[NZ*ZP];                  // 33KB
    __shared__ float Ed1[128], Ed2[128];          // e^d factors for own i rows
    __shared__ float Ms[48], vsS[4], vdS[4], cSs[12];

    int bt = blockIdx.y;
    int i0 = blockIdx.x * 128;
    int tid = threadIdx.x, wid = tid >> 5, lane = tid & 31;
    int lr = lane >> 2, lc = lane & 3;
    int ibase = i0 + wid*32;

    if (tid < 48) Ms[tid] = g_M[tid];
    else if (tid < 52) vsS[tid-48] = g_vs4[tid-48];
    else if (tid < 56) vdS[tid-52] = g_vd4[tid-52];
    else if (tid < 68) cSs[tid-56] = g_cS[tid-56];
    __syncthreads();

    // ---- prologue: Z + exp factors for all 512 j of this bt ----
    #pragma unroll
    for (int k = 0; k < 4; k++) {
        int j = tid + 128*k;
        float4 xv = __ldg((const float4*)(x + ((size_t)bt*Nn + j)*4));
        float as = xv.x*vsS[0] + xv.y*vsS[1] + xv.z*vsS[2] + xv.w*vsS[3];
        float ad = xv.x*vdS[0] + xv.y*vdS[1] + xv.z*vdS[2] + xv.w*vdS[3];
        #pragma unroll
        for (int g = 0; g < 12; g++) {
            float z = xv.x*Ms[g] + xv.y*Ms[12+g] + xv.z*Ms[24+g] + xv.w*Ms[36+g];
            smB[g*ZP + j] = __uint_as_float(cvt_tf32(z));
        }
        smB[12*ZP + j] = 1.0f;
        smB[13*ZP + j] = __expf(as);       // E1s
        smB[14*ZP + j] = __expf(0.2f*as);  // E2s
        smB[15*ZP + j] = 0.0f;
        if (k == (int)blockIdx.x) {        // j == i0 + tid
            Ed1[tid] = __expf(ad);
            Ed2[tid] = __expf(0.2f*ad);
        }
    }
    __syncthreads();

    const float* E1s = smB + 13*ZP;
    const float* E2s = smB + 14*ZP;

    float e1d[4], e2d[4];
    #pragma unroll
    for (int m = 0; m < 4; m++) {
        int ii = wid*32 + lr + 8*m;
        e1d[m] = Ed1[ii]; e2d[m] = Ed2[ii];
    }

    float acc[2][2][4];
    #pragma unroll
    for (int f = 0; f < 2; f++)
        #pragma unroll
        for (int nf = 0; nf < 2; nf++)
            #pragma unroll
            for (int r = 0; r < 4; r++) acc[f][nf][r] = 0.0f;

    const float* adjbt = adj + (size_t)bt*Nn*Nn;

    // ---- sync-free mainloop ----
    #pragma unroll 2
    for (int c = 0; c < 16; c++) {
        int j0 = c * 32;
        float av[4][8];
        #pragma unroll
        for (int ks = 0; ks < 4; ks++) {
            const float* r1 = adjbt + (size_t)(j0 + 8*ks + lc)*Nn + ibase + lr;
            const float* r2 = r1 + 4*Nn;
            #pragma unroll
            for (int f = 0; f < 2; f++) {
                av[ks][f*4+0] = r1[16*f];
                av[ks][f*4+1] = r1[16*f + 8];
                av[ks][f*4+2] = r2[16*f];
                av[ks][f*4+3] = r2[16*f + 8];
            }
        }
        bool diagchunk = (j0 == ibase);   // warp-uniform

        #pragma unroll
        for (int ks = 0; ks < 4; ks++) {
            int jl = j0 + 8*ks + lc;
            float E1a = E1s[jl],   E2a = E2s[jl];
            float E1b = E1s[jl+4], E2b = E2s[jl+4];
            uint32_t A[2][4];
            if (diagchunk) {
                #pragma unroll
                for (int f = 0; f < 2; f++)
                    #pragma unroll
                    for (int t = 0; t < 4; t++) {
                        int m = 2*f + (t & 1);
                        float E1 = (t < 2) ? E1a : E1b;
                        float E2 = (t < 2) ? E2a : E2b;
                        float a  = av[ks][f*4+t];
                        float w  = fmaxf(e1d[m]*E1, e2d[m]*E2);
                        int ig = ibase + lr + 16*f + 8*(t & 1);
                        int jg = jl + ((t < 2) ? 0 : 4);
                        w = ((a != 0.0f) || (ig == jg)) ? w : 0.0f;
                        A[f][t] = __float_as_uint(w);
                    }
            } else {
                #pragma unroll
                for (int f = 0; f < 2; f++)
                    #pragma unroll
                    for (int t = 0; t < 4; t++) {
                        int m = 2*f + (t & 1);
                        float E1 = (t < 2) ? E1a : E1b;
                        float E2 = (t < 2) ? E2a : E2b;
                        float a  = av[ks][f*4+t];
                        float w  = fmaxf(e1d[m]*E1, e2d[m]*E2);
                        A[f][t] = (a != 0.0f) ? __float_as_uint(w) : 0u;
                    }
            }
            #pragma unroll
            for (int nf = 0; nf < 2; nf++) {
                uint32_t b0 = __float_as_uint(smB[(lr + 8*nf)*ZP + jl]);
                uint32_t b1 = __float_as_uint(smB[(lr + 8*nf)*ZP + jl + 4]);
                mma_tf32(acc[0][nf], A[0], b0, b1);
                mma_tf32(acc[1][nf], A[1], b0, b1);
            }
        }
    }

    // epilogue: denominator = col 12 -> acc[f][1] regs 0/2 at lanes lc==2
    const unsigned FULL = 0xffffffffu;
    float inv[4];
    {
        int src = (lane & 28) | 2;
        float d0 = __shfl_sync(FULL, acc[0][1][0], src);
        float d1 = __shfl_sync(FULL, acc[0][1][2], src);
        float d2 = __shfl_sync(FULL, acc[1][1][0], src);
        float d3 = __shfl_sync(FULL, acc[1][1][2], src);
        inv[0] = 1.0f/d0; inv[1] = 1.0f/d1; inv[2] = 1.0f/d2; inv[3] = 1.0f/d3;
    }
    #pragma unroll
    for (int f = 0; f < 2; f++) {
        #pragma unroll
        for (int nf = 0; nf < 2; nf++) {
            int col = 8*nf + 2*lc;
            if (col + 1 < 12) {
                float b0 = cSs[col], b1 = cSs[col+1];
                size_t rowA = (size_t)bt*Nn + ibase + lr + 16*f;
                float2 v0 = make_float2(acc[f][nf][0]*inv[2*f]   + b0,
                                        acc[f][nf][1]*inv[2*f]   + b1);
                float2 v1 = make_float2(acc[f][nf][2]*inv[2*f+1] + b0,
                                        acc[f][nf][3]*inv[2*f+1] + b1);
                *(float2*)(g_gatesx + rowA*12 + col)     = v0;
                *(float2*)(g_gatesx + (rowA+8)*12 + col) = v1;
            }
        }
    }
}

// ---------------------------------------------------------------------------
// Kernel C: GRU recurrence. Four threads per sequence; writes [b][t][f][n].
// ---------------------------------------------------------------------------
__global__ __launch_bounds__(256) void gru_scan_kernel(const float* __restrict__ Whh,
                                const float* __restrict__ bhh) {
    __shared__ float WS[48], bS[12];
    int tid = threadIdx.x;
    if (tid < 48) WS[tid] = Whh[tid];
    if (tid < 12) bS[tid] = bhh[tid];
    __syncthreads();

    int gidx = blockIdx.x*256 + tid;
    int s = gidx >> 2, f = gidx & 3;
    int b = s >> 9, n = s & 511;
    int lane = tid & 31, base = lane & ~3;

    float Wr[4], Wz[4], Wn[4];
    #pragma unroll
    for (int k = 0; k < 4; k++) {
        Wr[k] = WS[f*4 + k];
        Wz[k] = WS[(4+f)*4 + k];
        Wn[k] = WS[(8+f)*4 + k];
    }
    float br = bS[f], bz = bS[4+f], bn = bS[8+f];

    const float* gx = g_gatesx + (size_t)s*(Tt*12) + f;
    float gv[24];
    #pragma unroll
    for (int t = 0; t < Tt; t++) {
        gv[3*t]   = gx[t*12];
        gv[3*t+1] = gx[t*12 + 4];
        gv[3*t+2] = gx[t*12 + 8];
    }

    const unsigned FULL = 0xffffffffu;
    float h = 0.0f;
    #pragma unroll
    for (int t = 0; t < Tt; t++) {
        float h0 = __shfl_sync(FULL, h, base);
        float h1 = __shfl_sync(FULL, h, base+1);
        float h2 = __shfl_sync(FULL, h, base+2);
        float h3 = __shfl_sync(FULL, h, base+3);
        float hr = br + Wr[0]*h0 + Wr[1]*h1 + Wr[2]*h2 + Wr[3]*h3;
        float hz = bz + Wz[0]*h0 + Wz[1]*h1 + Wz[2]*h2 + Wz[3]*h3;
        float hn = bn + Wn[0]*h0 + Wn[1]*h1 + Wn[2]*h2 + Wn[3]*h3;
        float r  = fast_sigmoid(gv[3*t]   + hr);
        float z  = fast_sigmoid(gv[3*t+1] + hz);
        float nc = fast_tanh(gv[3*t+2] + r*hn);
        h = (1.0f - z)*nc + z*h;
        g_gru[((size_t)b*32 + t*4 + f)*Nn + n] = h;   // [b][t][f][n]
    }
}

// ---------------------------------------------------------------------------
// Kernel D: Conv2d(8->12, 3x3, pad 1) over (N,4) + Linear(4->2), smem-tiled.
// grid 128 = 32 b x 4 n-tiles of 128; 128 threads, one per n; all 12 co/thread.
// ---------------------------------------------------------------------------
__global__ __launch_bounds__(128)
void conv_out_kernel(const float* __restrict__ convW,
                     const float* __restrict__ convb,
                     const float* __restrict__ outW,
                     const float* __restrict__ outb,
                     float* __restrict__ out) {
    __shared__ float gs[32][132];    // rows r=t*4+f, cols 0..129 = n0-1..n0+128
    __shared__ float cw[CO*Tt*9];
    __shared__ float cb[CO], ow[8], ob[2];
    int tid = threadIdx.x;
    int b  = blockIdx.x >> 2;
    int n0 = (blockIdx.x & 3) * 128;

    for (int k = tid; k < CO*Tt*9; k += 128) cw[k] = convW[k];
    if (tid < CO) cb[tid] = convb[tid];
    if (tid < 8)  ow[tid] = outW[tid];
    if (tid < 2)  ob[tid] = outb[tid];

    // stage tile: 32 rows x 130 cols, coalesced over n
    #pragma unroll
    for (int r = 0; r < 32; r++) {
        const float* src = g_gru + ((size_t)b*32 + r)*Nn;
        int n = n0 - 1 + tid;
        gs[r][tid] = (n >= 0 && n < Nn) ? src[n] : 0.0f;
        if (tid < 2) {
            int c2 = 128 + tid;
            int n2 = n0 - 1 + c2;
            gs[r][c2] = (n2 < Nn) ? src[n2] : 0.0f;
        }
    }
    __syncthreads();

    float y[CO][4];
    #pragma unroll
    for (int co = 0; co < CO; co++) {
        float c0 = cb[co];
        y[co][0] = c0; y[co][1] = c0; y[co][2] = c0; y[co][3] = c0;
    }

    #pragma unroll
    for (int ci = 0; ci < Tt; ci++) {
        float gm[4], g0[4], gp[4];
        #pragma unroll
        for (int f = 0; f < 4; f++) {
            int r = ci*4 + f;
            gm[f] = gs[r][tid];
            g0[f] = gs[r][tid+1];
            gp[f] = gs[r][tid+2];
        }
        #pragma unroll
        for (int co = 0; co < CO; co++) {
            const float* wk = cw + (co*Tt + ci)*9;
            float w00 = wk[0], w01 = wk[1], w02 = wk[2];
            float w10 = wk[3], w11 = wk[4], w12 = wk[5];
            float w20 = wk[6], w21 = wk[7], w22 = wk[8];
            float* yy = y[co];
            // kh=0 (gm)
            yy[0] = fmaf(w01, gm[0], fmaf(w02, gm[1], yy[0]));
            yy[1] = fmaf(w00, gm[0], fmaf(w01, gm[1], fmaf(w02, gm[2], yy[1])));
            yy[2] = fmaf(w00, gm[1], fmaf(w01, gm[2], fmaf(w02, gm[3], yy[2])));
            yy[3] = fmaf(w00, gm[2], fmaf(w01, gm[3], yy[3]));
            // kh=1 (g0)
            yy[0] = fmaf(w11, g0[0], fmaf(w12, g0[1], yy[0]));
            yy[1] = fmaf(w10, g0[0], fmaf(w11, g0[1], fmaf(w12, g0[2], yy[1])));
            yy[2] = fmaf(w10, g0[1], fmaf(w11, g0[2], fmaf(w12, g0[3], yy[2])));
            yy[3] = fmaf(w10, g0[2], fmaf(w11, g0[3], yy[3]));
            // kh=2 (gp)
            yy[0] = fmaf(w21, gp[0], fmaf(w22, gp[1], yy[0]));
            yy[1] = fmaf(w20, gp[0], fmaf(w21, gp[1], fmaf(w22, gp[2], yy[1])));
            yy[2] = fmaf(w20, gp[1], fmaf(w21, gp[2], fmaf(w22, gp[3], yy[2])));
            yy[3] = fmaf(w20, gp[2], fmaf(w21, gp[3], yy[3]));
        }
    }

    int n = n0 + tid;
    #pragma unroll
    for (int co = 0; co < CO; co++) {
        float o0 = ob[0] + y[co][0]*ow[0] + y[co][1]*ow[1]
                         + y[co][2]*ow[2] + y[co][3]*ow[3];
        float o1 = ob[1] + y[co][0]*ow[4] + y[co][1]*ow[5]
                         + y[co][2]*ow[6] + y[co][3]*ow[7];
        ((float2*)out)[((size_t)b*CO + co)*Nn + n] = make_float2(o0, o1);
    }
}

// ---------------------------------------------------------------------------
extern "C" void kernel_launch(void* const* d_in, const int* in_sizes, int n_in,
                              void* d_out, int out_size) {
    const float* x        = (const float*)d_in[0];
    const float* adj      = (const float*)d_in[1];
    const float* gat_W    = (const float*)d_in[2];
    const float* att_src  = (const float*)d_in[3];
    const float* att_dst  = (const float*)d_in[4];
    const float* gat_bias = (const float*)d_in[5];
    const float* gru_Wih  = (const float*)d_in[6];
    const float* gru_Whh  = (const float*)d_in[7];
    const float* gru_bih  = (const float*)d_in[8];
    const float* gru_bhh  = (const float*)d_in[9];
    const float* conv_W   = (const float*)d_in[10];
    const float* conv_b   = (const float*)d_in[11];
    const float* out_W    = (const float*)d_in[12];
    const float* out_b    = (const float*)d_in[13];
    float* out = (float*)d_out;

    precompute_kernel<<<1, 128>>>(gat_W, att_src, att_dst, gru_Wih, gru_bih, gat_bias);
    gat_fused<<<dim3(4, Bb*Tt), 128>>>(x, adj);
    gru_scan_kernel<<<SEQS*4/256, 256>>>(gru_Whh, gru_bhh);
    conv_out_kernel<<<128, 128>>>(conv_W, conv_b, out_W, out_b, out);
}